// round 3
// baseline (speedup 1.0000x reference)
#include <cuda_runtime.h>
#include <cuda.h>
#include <cuda_bf16.h>
#include <cstdint>
#include <cstdio>

// ============================================================================
// QuantizedLinear: out[t,o] = (sum_k x[t,k]*(w[o,k]-zp[o])) * scale[o] + bias[o]
//   M=TOKENS=4096, N=OUT_F=11008, K=IN_F=4096
//
// Numerics (both paths): int8 weights -> bf16 EXACT (|w|<=128 fits 8-bit
// significand). Input split x = hi + lo (bf16 each). Two bf16 GEMMs into one
// fp32 accumulator => ~16 effective mantissa bits, rel_err ~1e-5.
// zero_point handled exactly via per-row input sums.
//
// Two compile-time paths:
//   - tcgen05 (only if ptxas target is sm_100a/sm_103a: feature macro set)
//   - legacy mma.sync.m16n8k16 bf16 (works on plain sm_100 target)
// Both kernels always launched; the unavailable one is an empty stub.
// ============================================================================

#define TOKENS 4096
#define IN_F   4096
#define OUT_F  11008

#if defined(__CUDA_ARCH__) && (defined(__CUDA_ARCH_FEAT_SM100_ALL) || defined(__CUDA_ARCH_FEAT_SM103_ALL) || defined(__CUDA_ARCH_FEAT_SM101_ALL))
#define HAVE_TCGEN05 1
#else
#define HAVE_TCGEN05 0
#endif

// ---- scratch (device globals: no allocation allowed) ----
__device__ __align__(1024) __nv_bfloat16 g_W  [(size_t)OUT_F  * IN_F];
__device__ __align__(1024) __nv_bfloat16 g_Ahi[(size_t)TOKENS * IN_F];
__device__ __align__(1024) __nv_bfloat16 g_Alo[(size_t)TOKENS * IN_F];
__device__ float g_rowsum[TOKENS];

// ============================================================================
// Common helpers
// ============================================================================
__device__ __forceinline__ uint32_t smem_u32(const void* p) {
    uint32_t a;
    asm("{ .reg .u64 t; cvta.to.shared.u64 t, %1; cvt.u32.u64 %0, t; }"
        : "=r"(a) : "l"(p));
    return a;
}

// ============================================================================
// Preprocessing kernels
// ============================================================================
__global__ void k_convert_w(const int4* __restrict__ w4, uint2* __restrict__ W, int n4) {
    int i = blockIdx.x * blockDim.x + threadIdx.x;
    if (i >= n4) return;
    int4 v = w4[i];
    union { __nv_bfloat16 h[4]; uint2 u; } o;
    o.h[0] = __float2bfloat16((float)v.x);   // |w|<=128: exact in bf16
    o.h[1] = __float2bfloat16((float)v.y);
    o.h[2] = __float2bfloat16((float)v.z);
    o.h[3] = __float2bfloat16((float)v.w);
    W[i] = o.u;
}

__global__ void k_convert_x(const float4* __restrict__ x4, uint2* __restrict__ hi,
                            uint2* __restrict__ lo, int n4) {
    int i = blockIdx.x * blockDim.x + threadIdx.x;
    if (i >= n4) return;
    float4 v = x4[i];
    union { __nv_bfloat16 h[4]; uint2 u; } H, L;
    const float* f = &v.x;
#pragma unroll
    for (int j = 0; j < 4; j++) {
        __nv_bfloat16 h = __float2bfloat16(f[j]);
        H.h[j] = h;
        L.h[j] = __float2bfloat16(f[j] - __bfloat162float(h));
    }
    hi[i] = H.u;
    lo[i] = L.u;
}

__global__ void k_rowsum(const float* __restrict__ x, float* __restrict__ rs) {
    int row = blockIdx.x;
    const float* p = x + (size_t)row * IN_F;
    float s = 0.f;
    for (int k = threadIdx.x; k < IN_F; k += 256) s += p[k];
#pragma unroll
    for (int o = 16; o > 0; o >>= 1) s += __shfl_xor_sync(0xffffffffu, s, o);
    __shared__ float red[8];
    if ((threadIdx.x & 31) == 0) red[threadIdx.x >> 5] = s;
    __syncthreads();
    if (threadIdx.x < 8) {
        float v = red[threadIdx.x];
#pragma unroll
        for (int o = 4; o > 0; o >>= 1) v += __shfl_xor_sync(0xffu, v, o);
        if (threadIdx.x == 0) rs[row] = v;
    }
}

// ============================================================================
// PATH A: tcgen05 (compiled only when the a-variant target is available)
// ============================================================================
#define TC_BM 128
#define TC_BN 256
#define TC_KC 64
#define TC_NCHUNK (IN_F / TC_KC)
#define TC_STAGES 3

#define OFF_TMEM     0
#define OFF_FULL(s)  (16 + 8*(s))
#define OFF_EMPTY(s) (40 + 8*(s))
#define OFF_DONE     64
#define OFF_SCALE    128
#define OFF_BIAS     (128 + 1024)
#define OFF_ZP       (128 + 2048)
#define OFF_STAGE0   4096
#define TC_STAGE_STRIDE 65536
#define ST_B(s)      (OFF_STAGE0 + (s)*TC_STAGE_STRIDE)
#define ST_AH(s)     (ST_B(s) + 32768)
#define ST_AL(s)     (ST_B(s) + 49152)
#define TC_STAGE_BYTES  65536
#define TC_SMEM_TOTAL   (OFF_STAGE0 + TC_STAGES*TC_STAGE_STRIDE)

#define MMA_IDESC ((1u<<4) | (1u<<7) | (1u<<10) | ((TC_BN/8)<<17) | ((TC_BM/16)<<24))

#if HAVE_TCGEN05
#define MBAR_INIT(addr, cnt) \
    asm volatile("mbarrier.init.shared.b64 [%0], %1;" :: "r"(addr), "r"((uint32_t)(cnt)) : "memory")
#define MBAR_EXPECT(addr, bytes) \
    asm volatile("mbarrier.arrive.expect_tx.shared.b64 _, [%0], %1;" :: "r"(addr), "r"((uint32_t)(bytes)) : "memory")

__device__ __forceinline__ void mbar_wait(uint32_t addr, uint32_t parity) {
    uint32_t done;
    asm volatile(
        "{\n\t.reg .pred p;\n\t"
        "mbarrier.try_wait.parity.acquire.cta.shared::cta.b64 p, [%1], %2;\n\t"
        "selp.b32 %0, 1, 0, p;\n\t}"
        : "=r"(done) : "r"(addr), "r"(parity) : "memory");
    if (!done) {
        asm volatile(
            "{\n\t.reg .pred P1;\n\t"
            "WL_%=:\n\t"
            "mbarrier.try_wait.parity.acquire.cta.shared::cta.b64 P1, [%0], %1, 0x989680;\n\t"
            "@P1 bra.uni WD_%=;\n\t"
            "bra.uni WL_%=;\n\t"
            "WD_%=:\n\t}"
            :: "r"(addr), "r"(parity) : "memory");
    }
}

__device__ __forceinline__ void tma_ld_2d(uint32_t smem, const void* map, int x, int y, uint32_t mbar) {
    asm volatile(
        "cp.async.bulk.tensor.2d.shared::cta.global.tile.mbarrier::complete_tx::bytes "
        "[%0], [%1, {%2, %3}], [%4];"
        :: "r"(smem), "l"(map), "r"(x), "r"(y), "r"(mbar) : "memory");
}

__device__ __forceinline__ uint64_t mk_desc(uint32_t addr) {
    const uint64_t BASE = (2ull << 61) | (1ull << 46) | (64ull << 32) | (1ull << 16);
    return BASE | ((uint64_t)(addr >> 4) & 0x3FFF);
}

__device__ __forceinline__ void mma_f16_ss_cg1(uint32_t d, uint64_t a, uint64_t b,
                                               uint32_t idesc, uint32_t en) {
    asm volatile(
        "{\n\t.reg .pred p;\n\t"
        "setp.ne.u32 p, %4, 0;\n\t"
        "tcgen05.mma.cta_group::1.kind::f16 [%0], %1, %2, %3, {%5, %5, %5, %5}, p;\n\t}"
        :: "r"(d), "l"(a), "l"(b), "r"(idesc), "r"(en), "r"(0u) : "memory");
}

__device__ __forceinline__ void tc_commit(uint32_t mbar) {
    asm volatile(
        "tcgen05.commit.cta_group::1.mbarrier::arrive::one.shared::cluster.b64 [%0];"
        :: "r"(mbar) : "memory");
}

#define TC_LD_X32(r, tmem_addr) \
    asm volatile( \
        "tcgen05.ld.sync.aligned.32x32b.x32.b32 " \
        "{%0, %1, %2, %3, %4, %5, %6, %7, " \
        " %8, %9, %10, %11, %12, %13, %14, %15, " \
        " %16, %17, %18, %19, %20, %21, %22, %23, " \
        " %24, %25, %26, %27, %28, %29, %30, %31}, [%32];" \
        : "=r"((r)[0]),  "=r"((r)[1]),  "=r"((r)[2]),  "=r"((r)[3]), \
          "=r"((r)[4]),  "=r"((r)[5]),  "=r"((r)[6]),  "=r"((r)[7]), \
          "=r"((r)[8]),  "=r"((r)[9]),  "=r"((r)[10]), "=r"((r)[11]), \
          "=r"((r)[12]), "=r"((r)[13]), "=r"((r)[14]), "=r"((r)[15]), \
          "=r"((r)[16]), "=r"((r)[17]), "=r"((r)[18]), "=r"((r)[19]), \
          "=r"((r)[20]), "=r"((r)[21]), "=r"((r)[22]), "=r"((r)[23]), \
          "=r"((r)[24]), "=r"((r)[25]), "=r"((r)[26]), "=r"((r)[27]), \
          "=r"((r)[28]), "=r"((r)[29]), "=r"((r)[30]), "=r"((r)[31]) \
        : "r"(tmem_addr))
#endif  // HAVE_TCGEN05

__global__ void __launch_bounds__(128, 1) qlinear_tc(
    const __grid_constant__ CUtensorMap tmAh,
    const __grid_constant__ CUtensorMap tmAl,
    const __grid_constant__ CUtensorMap tmB,
    const float* __restrict__ scales,
    const float* __restrict__ zps,
    const float* __restrict__ biasv,
    const float* __restrict__ rowsum,
    float* __restrict__ out)
{
#if HAVE_TCGEN05
    extern __shared__ __align__(1024) char smem[];
    const uint32_t sb = smem_u32(smem);
    const int tid = threadIdx.x;
    const int wid = tid >> 5, lid = tid & 31;
    const int cbase = blockIdx.x * TC_BN;
    const int rbase = blockIdx.y * TC_BM;

    if (wid == 0) {
        asm volatile("tcgen05.alloc.cta_group::1.sync.aligned.shared::cta.b32 [%0], %1;"
                     :: "r"(sb + OFF_TMEM), "r"(256u) : "memory");
        asm volatile("tcgen05.relinquish_alloc_permit.cta_group::1.sync.aligned;");
    }
    if (tid == 0) {
        for (int s = 0; s < TC_STAGES; s++) {
            MBAR_INIT(sb + OFF_FULL(s), 1);
            MBAR_INIT(sb + OFF_EMPTY(s), 1);
        }
        MBAR_INIT(sb + OFF_DONE, 1);
        asm volatile("fence.proxy.async.shared::cta;" ::: "memory");
    }

    float* s_sc = (float*)(smem + OFF_SCALE);
    float* s_bi = (float*)(smem + OFF_BIAS);
    float* s_zp = (float*)(smem + OFF_ZP);
    for (int i = tid; i < TC_BN; i += 128) {
        s_sc[i] = scales[cbase + i];
        s_bi[i] = biasv[cbase + i];
        s_zp[i] = zps[cbase + i];
    }
    __syncthreads();

    uint32_t tmem;
    asm volatile("ld.shared.b32 %0, [%1];" : "=r"(tmem) : "r"(sb + OFF_TMEM));

    if (tid == 0) {
        for (int i = 0; i < TC_STAGES; i++) {
            MBAR_EXPECT(sb + OFF_FULL(i), TC_STAGE_BYTES);
            tma_ld_2d(sb + ST_B(i),  &tmB,  i * TC_KC, cbase, sb + OFF_FULL(i));
            tma_ld_2d(sb + ST_AH(i), &tmAh, i * TC_KC, rbase, sb + OFF_FULL(i));
            tma_ld_2d(sb + ST_AL(i), &tmAl, i * TC_KC, rbase, sb + OFF_FULL(i));
        }
        int cs = 0, cp = 0, ps = 0, pp = 0;
        for (int c = 0; c < TC_NCHUNK; c++) {
            mbar_wait(sb + OFF_FULL(cs), cp);
            uint64_t bd  = mk_desc(sb + ST_B(cs));
            uint64_t ahd = mk_desc(sb + ST_AH(cs));
            uint64_t ald = mk_desc(sb + ST_AL(cs));
#pragma unroll
            for (int ks = 0; ks < 4; ks++)
                mma_f16_ss_cg1(tmem, ahd + 2*ks, bd + 2*ks, MMA_IDESC, (c | ks) ? 1u : 0u);
#pragma unroll
            for (int ks = 0; ks < 4; ks++)
                mma_f16_ss_cg1(tmem, ald + 2*ks, bd + 2*ks, MMA_IDESC, 1u);
            if (c == TC_NCHUNK - 1) tc_commit(sb + OFF_DONE);
            else                    tc_commit(sb + OFF_EMPTY(cs));
            cs++; if (cs == TC_STAGES) { cs = 0; cp ^= 1; }
            if (c >= 1) {
                int nc = c + TC_STAGES - 1;
                if (nc < TC_NCHUNK) {
                    mbar_wait(sb + OFF_EMPTY(ps), pp);
                    MBAR_EXPECT(sb + OFF_FULL(ps), TC_STAGE_BYTES);
                    tma_ld_2d(sb + ST_B(ps),  &tmB,  nc * TC_KC, cbase, sb + OFF_FULL(ps));
                    tma_ld_2d(sb + ST_AH(ps), &tmAh, nc * TC_KC, rbase, sb + OFF_FULL(ps));
                    tma_ld_2d(sb + ST_AL(ps), &tmAl, nc * TC_KC, rbase, sb + OFF_FULL(ps));
                    ps++; if (ps == TC_STAGES) { ps = 0; pp ^= 1; }
                }
            }
        }
    }

    mbar_wait(sb + OFF_DONE, 0);
    asm volatile("tcgen05.fence::after_thread_sync;" ::: "memory");

    const int row = rbase + wid * 32 + lid;
    const float rs = rowsum[row];
    float* orow = out + (size_t)row * OUT_F + cbase;
#pragma unroll 1
    for (int blk = 0; blk < 8; blk++) {
        uint32_t r[32];
        TC_LD_X32(r, tmem + blk * 32);
        asm volatile("tcgen05.wait::ld.sync.aligned;" ::: "memory");
#pragma unroll
        for (int c = 0; c < 32; c += 4) {
            int col = blk * 32 + c;
            float4 v;
            v.x = (__uint_as_float(r[c+0]) - s_zp[col+0] * rs) * s_sc[col+0] + s_bi[col+0];
            v.y = (__uint_as_float(r[c+1]) - s_zp[col+1] * rs) * s_sc[col+1] + s_bi[col+1];
            v.z = (__uint_as_float(r[c+2]) - s_zp[col+2] * rs) * s_sc[col+2] + s_bi[col+2];
            v.w = (__uint_as_float(r[c+3]) - s_zp[col+3] * rs) * s_sc[col+3] + s_bi[col+3];
            *reinterpret_cast<float4*>(orow + col) = v;
        }
    }
    __syncthreads();
    if (wid == 0) {
        asm volatile("tcgen05.dealloc.cta_group::1.sync.aligned.b32 %0, %1;"
                     :: "r"(tmem), "r"(256u));
    }
#else
    (void)tmAh; (void)tmAl; (void)tmB; (void)scales; (void)zps; (void)biasv;
    (void)rowsum; (void)out;
#endif
}

// ============================================================================
// PATH B: legacy mma.sync.m16n8k16 bf16 (valid on plain sm_100 target)
//   CTA tile 128x128, 8 warps (warp tile 64x32), KC=32, 4-stage cp.async.
// ============================================================================
#define MM_BM 128
#define MM_BN 128
#define MM_KC 32
#define MM_KT (IN_F / MM_KC)          // 128
#define MM_NSTAGE 4
#define MM_SA_HI 0
#define MM_SA_LO 8192
#define MM_SB    16384
#define MM_STAGE_BYTES 24576
#define MM_PARAMS (MM_NSTAGE * MM_STAGE_BYTES)     // 98304
#define MM_SMEM_TOTAL (MM_PARAMS + 3 * MM_BN * 4)  // +1536 = 99840

#if !HAVE_TCGEN05
__device__ __forceinline__ void cp_async16(uint32_t saddr, const void* gaddr) {
    asm volatile("cp.async.cg.shared.global [%0], [%1], 16;" :: "r"(saddr), "l"(gaddr));
}
__device__ __forceinline__ void cp_commit() { asm volatile("cp.async.commit_group;"); }
__device__ __forceinline__ void cp_wait2()  { asm volatile("cp.async.wait_group 2;"); }

// swizzled smem offset for (row, 16B-chunk) in a 128x32 bf16 tile (64B rows)
__device__ __forceinline__ uint32_t sw_off(int row, int ch) {
    return (uint32_t)(row * 64 + ((ch ^ ((row >> 1) & 3)) << 4));
}

__device__ __forceinline__ void ldsm_x4(uint32_t* r, uint32_t addr) {
    asm volatile("ldmatrix.sync.aligned.m8n8.x4.shared.b16 {%0,%1,%2,%3}, [%4];"
                 : "=r"(r[0]), "=r"(r[1]), "=r"(r[2]), "=r"(r[3]) : "r"(addr));
}

__device__ __forceinline__ void mma16816(float* d, const uint32_t* a, uint32_t b0, uint32_t b1) {
    asm volatile(
        "mma.sync.aligned.m16n8k16.row.col.f32.bf16.bf16.f32 "
        "{%0,%1,%2,%3}, {%4,%5,%6,%7}, {%8,%9}, {%0,%1,%2,%3};"
        : "+f"(d[0]), "+f"(d[1]), "+f"(d[2]), "+f"(d[3])
        : "r"(a[0]), "r"(a[1]), "r"(a[2]), "r"(a[3]), "r"(b0), "r"(b1));
}

__device__ __forceinline__ void mm_issue_stage(
    uint32_t sbase, int slot, int kbase, int rbase, int cbase, int tid,
    const __nv_bfloat16* Ah, const __nv_bfloat16* Al, const __nv_bfloat16* W)
{
    uint32_t st = sbase + slot * MM_STAGE_BYTES;
#pragma unroll
    for (int r = 0; r < 2; r++) {
        int u = tid + r * 256;
        int row = u >> 2, ch = u & 3;
        uint32_t so = sw_off(row, ch);
        size_t goA = (size_t)(rbase + row) * IN_F + kbase + ch * 8;
        size_t goB = (size_t)(cbase + row) * IN_F + kbase + ch * 8;
        cp_async16(st + MM_SA_HI + so, Ah + goA);
        cp_async16(st + MM_SA_LO + so, Al + goA);
        cp_async16(st + MM_SB    + so, W  + goB);
    }
    cp_commit();
}
#endif  // !HAVE_TCGEN05

__global__ void __launch_bounds__(256, 2) qlinear_mma(
    const __nv_bfloat16* __restrict__ Ah,
    const __nv_bfloat16* __restrict__ Al,
    const __nv_bfloat16* __restrict__ W,
    const float* __restrict__ scales,
    const float* __restrict__ zps,
    const float* __restrict__ biasv,
    const float* __restrict__ rowsum,
    float* __restrict__ out)
{
#if !HAVE_TCGEN05
    extern __shared__ __align__(128) char smem[];
    const uint32_t sb = smem_u32(smem);
    const int tid  = threadIdx.x;
    const int lane = tid & 31;
    const int wid  = tid >> 5;
    const int wm   = wid >> 2;        // 0..1 : warp M tile (64 rows)
    const int wn   = wid & 3;         // 0..3 : warp N tile (32 cols)
    const int cbase = blockIdx.x * MM_BN;
    const int rbase = blockIdx.y * MM_BM;

    // epilogue params -> smem
    float* s_sc = (float*)(smem + MM_PARAMS);
    float* s_zp = s_sc + MM_BN;
    float* s_bi = s_zp + MM_BN;
    for (int i = tid; i < MM_BN; i += 256) {
        s_sc[i] = scales[cbase + i];
        s_zp[i] = zps[cbase + i];
        s_bi[i] = biasv[cbase + i];
    }

    // prologue: fill NSTAGE-1 stages
#pragma unroll
    for (int s = 0; s < MM_NSTAGE - 1; s++)
        mm_issue_stage(sb, s, s * MM_KC, rbase, cbase, tid, Ah, Al, W);

    float acc[4][4][4];
#pragma unroll
    for (int i = 0; i < 4; i++)
#pragma unroll
        for (int j = 0; j < 4; j++)
#pragma unroll
            for (int k = 0; k < 4; k++) acc[i][j][k] = 0.f;

    // ldmatrix lane addressing (row/chunk components fixed per thread)
    const int lrow = lane & 15;           // row within 16-row tile
    const int lsel = lane >> 4;           // 0/1 -> chunk +0/+1

    for (int kt = 0; kt < MM_KT; kt++) {
        cp_wait2();
        __syncthreads();
        const uint32_t st = sb + (kt & (MM_NSTAGE - 1)) * MM_STAGE_BYTES;

#pragma unroll
        for (int kh = 0; kh < 2; kh++) {
            const int chunk = kh * 2 + lsel;
            uint32_t af[4][4], bfr[2][4];
            // B fragments (shared by hi and lo passes)
#pragma unroll
            for (int ng = 0; ng < 2; ng++) {
                const int row = wn * 32 + ng * 16 + lrow;
                ldsm_x4(bfr[ng], st + MM_SB + sw_off(row, chunk));
            }
            // ---- hi pass ----
#pragma unroll
            for (int mt = 0; mt < 4; mt++) {
                const int row = wm * 64 + mt * 16 + lrow;
                ldsm_x4(af[mt], st + MM_SA_HI + sw_off(row, chunk));
            }
#pragma unroll
            for (int mt = 0; mt < 4; mt++)
#pragma unroll
                for (int nt = 0; nt < 4; nt++) {
                    const int ng = nt >> 1, sel = nt & 1;
                    mma16816(acc[mt][nt], af[mt], bfr[ng][sel], bfr[ng][sel + 2]);
                }
            // ---- lo pass (reuse af regs) ----
#pragma unroll
            for (int mt = 0; mt < 4; mt++) {
                const int row = wm * 64 + mt * 16 + lrow;
                ldsm_x4(af[mt], st + MM_SA_LO + sw_off(row, chunk));
            }
#pragma unroll
            for (int mt = 0; mt < 4; mt++)
#pragma unroll
                for (int nt = 0; nt < 4; nt++) {
                    const int ng = nt >> 1, sel = nt & 1;
                    mma16816(acc[mt][nt], af[mt], bfr[ng][sel], bfr[ng][sel + 2]);
                }
        }

        const int nk = kt + MM_NSTAGE - 1;
        if (nk < MM_KT)
            mm_issue_stage(sb, nk & (MM_NSTAGE - 1), nk * MM_KC, rbase, cbase, tid, Ah, Al, W);
    }

    // ---- epilogue ----
    float rs0[4], rs1[4];
#pragma unroll
    for (int mt = 0; mt < 4; mt++) {
        const int r0 = rbase + wm * 64 + mt * 16 + (lane >> 2);
        rs0[mt] = __ldg(rowsum + r0);
        rs1[mt] = __ldg(rowsum + r0 + 8);
    }
#pragma unroll
    for (int mt = 0; mt < 4; mt++) {
        const int r0 = rbase + wm * 64 + mt * 16 + (lane >> 2);
#pragma unroll
        for (int nt = 0; nt < 4; nt++) {
            const int c  = wn * 32 + nt * 8 + 2 * (lane & 3);
            const int gc = cbase + c;
            float2 v0, v1;
            v0.x = (acc[mt][nt][0] - s_zp[c]   * rs0[mt]) * s_sc[c]   + s_bi[c];
            v0.y = (acc[mt][nt][1] - s_zp[c+1] * rs0[mt]) * s_sc[c+1] + s_bi[c+1];
            v1.x = (acc[mt][nt][2] - s_zp[c]   * rs1[mt]) * s_sc[c]   + s_bi[c];
            v1.y = (acc[mt][nt][3] - s_zp[c+1] * rs1[mt]) * s_sc[c+1] + s_bi[c+1];
            *reinterpret_cast<float2*>(out + (size_t)r0 * OUT_F + gc)       = v0;
            *reinterpret_cast<float2*>(out + (size_t)(r0 + 8) * OUT_F + gc) = v1;
        }
    }
#else
    (void)Ah; (void)Al; (void)W; (void)scales; (void)zps; (void)biasv;
    (void)rowsum; (void)out;
#endif
}

// ============================================================================
// Host launcher
// ============================================================================
typedef CUresult (*tme_fn_t)(CUtensorMap*, CUtensorMapDataType, cuuint32_t, void*,
                             const cuuint64_t*, const cuuint64_t*,
                             const cuuint32_t*, const cuuint32_t*,
                             CUtensorMapInterleave, CUtensorMapSwizzle,
                             CUtensorMapL2promotion, CUtensorMapFloatOOBfill);

extern "C" void kernel_launch(void* const* d_in, const int* in_sizes, int n_in,
                              void* d_out, int out_size) {
    const float* input  = (const float*)d_in[0];
    const int*   w      = (const int*)d_in[1];
    const float* scales = (const float*)d_in[2];
    const float* zps    = (const float*)d_in[3];
    const float* bias   = (const float*)d_in[4];
    float* out = (float*)d_out;
    (void)in_sizes; (void)n_in; (void)out_size;

    void *pW = nullptr, *pAh = nullptr, *pAl = nullptr, *pRs = nullptr;
    cudaGetSymbolAddress(&pW,  g_W);
    cudaGetSymbolAddress(&pAh, g_Ahi);
    cudaGetSymbolAddress(&pAl, g_Alo);
    cudaGetSymbolAddress(&pRs, g_rowsum);

    tme_fn_t encode = nullptr;
    cudaDriverEntryPointQueryResult qr;
    cudaGetDriverEntryPoint("cuTensorMapEncodeTiled", (void**)&encode,
                            cudaEnableDefault, &qr);

    CUtensorMap mAh, mAl, mB;
    __builtin_memset(&mAh, 0, sizeof(mAh));
    __builtin_memset(&mAl, 0, sizeof(mAl));
    __builtin_memset(&mB, 0, sizeof(mB));
    if (encode) {
        {
            cuuint64_t dims[2]    = { IN_F, TOKENS };
            cuuint64_t strides[1] = { IN_F * sizeof(__nv_bfloat16) };
            cuuint32_t box[2]     = { TC_KC, TC_BM };
            cuuint32_t es[2]      = { 1, 1 };
            encode(&mAh, CU_TENSOR_MAP_DATA_TYPE_BFLOAT16, 2, pAh, dims, strides, box, es,
                   CU_TENSOR_MAP_INTERLEAVE_NONE, CU_TENSOR_MAP_SWIZZLE_128B,
                   CU_TENSOR_MAP_L2_PROMOTION_L2_128B, CU_TENSOR_MAP_FLOAT_OOB_FILL_NONE);
            encode(&mAl, CU_TENSOR_MAP_DATA_TYPE_BFLOAT16, 2, pAl, dims, strides, box, es,
                   CU_TENSOR_MAP_INTERLEAVE_NONE, CU_TENSOR_MAP_SWIZZLE_128B,
                   CU_TENSOR_MAP_L2_PROMOTION_L2_128B, CU_TENSOR_MAP_FLOAT_OOB_FILL_NONE);
        }
        {
            cuuint64_t dims[2]    = { IN_F, OUT_F };
            cuuint64_t strides[1] = { IN_F * sizeof(__nv_bfloat16) };
            cuuint32_t box[2]     = { TC_KC, TC_BN };
            cuuint32_t es[2]      = { 1, 1 };
            encode(&mB, CU_TENSOR_MAP_DATA_TYPE_BFLOAT16, 2, pW, dims, strides, box, es,
                   CU_TENSOR_MAP_INTERLEAVE_NONE, CU_TENSOR_MAP_SWIZZLE_128B,
                   CU_TENSOR_MAP_L2_PROMOTION_L2_128B, CU_TENSOR_MAP_FLOAT_OOB_FILL_NONE);
        }
    }

    cudaFuncSetAttribute(qlinear_tc, cudaFuncAttributeMaxDynamicSharedMemorySize,
                         TC_SMEM_TOTAL);
    cudaFuncSetAttribute(qlinear_mma, cudaFuncAttributeMaxDynamicSharedMemorySize,
                         MM_SMEM_TOTAL);

    // preprocessing
    {
        int n4 = (OUT_F * IN_F) / 4;
        k_convert_w<<<(n4 + 255) / 256, 256>>>((const int4*)w, (uint2*)pW, n4);
    }
    {
        int n4 = (TOKENS * IN_F) / 4;
        k_convert_x<<<(n4 + 255) / 256, 256>>>((const float4*)input,
                                               (uint2*)pAh, (uint2*)pAl, n4);
    }
    k_rowsum<<<TOKENS, 256>>>(input, (float*)pRs);

    // PATH A (stub unless a-variant target): 43 x 32 tiles of 128x256
    {
        dim3 grid(OUT_F / TC_BN, TOKENS / TC_BM);
        qlinear_tc<<<grid, 128, TC_SMEM_TOTAL>>>(mAh, mAl, mB, scales, zps, bias,
                                                 (const float*)pRs, out);
    }
    // PATH B (stub when tcgen05 available): 86 x 32 tiles of 128x128
    {
        dim3 grid(OUT_F / MM_BN, TOKENS / MM_BM);
        qlinear_mma<<<grid, 256, MM_SMEM_TOTAL>>>((const __nv_bfloat16*)pAh,
                                                  (const __nv_bfloat16*)pAl,
                                                  (const __nv_bfloat16*)pW,
                                                  scales, zps, bias,
                                                  (const float*)pRs, out);
    }
}

// round 4
// speedup vs baseline: 1.1855x; 1.1855x over previous
#include <cuda_runtime.h>
#include <cuda.h>
#include <cuda_bf16.h>
#include <cstdint>
#include <cstdio>

// ============================================================================
// QuantizedLinear: out[t,o] = (sum_k x[t,k]*(w[o,k]-zp[o])) * scale[o] + bias[o]
//   M=TOKENS=4096, N=OUT_F=11008, K=IN_F=4096
//
// tcgen05 kernel, tile 128x512 (two N=256 MMA regions, D = all 512 TMEM cols),
// KC=32, SW64 swizzle, 4-stage TMA pipeline, warp-specialized:
//   warps 0-3 epilogue, warp 4 TMA producer, warp 5 MMA driver.
// Numerics: int8 W -> bf16 exact; input split hi+lo bf16; 2 GEMMs, fp32 acc.
// ============================================================================

#define TOKENS 4096
#define IN_F   4096
#define OUT_F  11008

#define BM 128
#define BN 512
#define KC 32
#define NCH (IN_F / KC)        // 128 chunks
#define NST 4                  // pipeline stages

#if defined(__CUDA_ARCH__) && (defined(__CUDA_ARCH_FEAT_SM100_ALL) || defined(__CUDA_ARCH_FEAT_SM103_ALL) || defined(__CUDA_ARCH_FEAT_SM101_ALL))
#define HAVE_TCGEN05 1
#else
#define HAVE_TCGEN05 0
#endif

// ---- dynamic SMEM layout ----
#define OFF_TMEM     0
#define OFF_FULL(s)  (16 + 8*(s))
#define OFF_EMPTY(s) (48 + 8*(s))
#define OFF_DONE     80
#define STAGE_STRIDE 49152            // Ahi 8K + Alo 8K + B 32K
#define OFF_ST(s)    (1024 + (s)*STAGE_STRIDE)
#define ST_AH        0
#define ST_AL        8192
#define ST_B         16384
#define OFF_PRM      (1024 + NST*STAGE_STRIDE)   // 197632
#define SMEM_TOTAL   (OFF_PRM + 3*BN*4)          // 203776

// idesc kind::f16: dtype=F32(bit4), atype=BF16(bit7), btype=BF16(bit10),
// N/8 at [17:22] (N=256 per MMA region), M/16 at [24:28]
#define MMA_IDESC ((1u<<4) | (1u<<7) | (1u<<10) | ((256/8)<<17) | ((BM/16)<<24))

// ---- scratch (device globals: no allocation allowed) ----
__device__ __align__(1024) __nv_bfloat16 g_W  [(size_t)OUT_F  * IN_F];
__device__ __align__(1024) __nv_bfloat16 g_Ahi[(size_t)TOKENS * IN_F];
__device__ __align__(1024) __nv_bfloat16 g_Alo[(size_t)TOKENS * IN_F];
__device__ float g_rowsum[TOKENS];

// ============================================================================
// Common helpers
// ============================================================================
__device__ __forceinline__ uint32_t smem_u32(const void* p) {
    uint32_t a;
    asm("{ .reg .u64 t; cvta.to.shared.u64 t, %1; cvt.u32.u64 %0, t; }"
        : "=r"(a) : "l"(p));
    return a;
}

// ============================================================================
// Preprocessing kernels
// ============================================================================
__global__ void k_convert_w(const int4* __restrict__ w4, uint2* __restrict__ W, int n4) {
    int i = blockIdx.x * blockDim.x + threadIdx.x;
    if (i >= n4) return;
    int4 v = w4[i];
    union { __nv_bfloat16 h[4]; uint2 u; } o;
    o.h[0] = __float2bfloat16((float)v.x);   // |w|<=128: exact in bf16
    o.h[1] = __float2bfloat16((float)v.y);
    o.h[2] = __float2bfloat16((float)v.z);
    o.h[3] = __float2bfloat16((float)v.w);
    W[i] = o.u;
}

__global__ void k_convert_x(const float4* __restrict__ x4, uint2* __restrict__ hi,
                            uint2* __restrict__ lo, int n4) {
    int i = blockIdx.x * blockDim.x + threadIdx.x;
    if (i >= n4) return;
    float4 v = x4[i];
    union { __nv_bfloat16 h[4]; uint2 u; } H, L;
    const float* f = &v.x;
#pragma unroll
    for (int j = 0; j < 4; j++) {
        __nv_bfloat16 h = __float2bfloat16(f[j]);
        H.h[j] = h;
        L.h[j] = __float2bfloat16(f[j] - __bfloat162float(h));
    }
    hi[i] = H.u;
    lo[i] = L.u;
}

__global__ void k_rowsum(const float* __restrict__ x, float* __restrict__ rs) {
    int row = blockIdx.x;
    const float* p = x + (size_t)row * IN_F;
    float s = 0.f;
    for (int k = threadIdx.x; k < IN_F; k += 256) s += p[k];
#pragma unroll
    for (int o = 16; o > 0; o >>= 1) s += __shfl_xor_sync(0xffffffffu, s, o);
    __shared__ float red[8];
    if ((threadIdx.x & 31) == 0) red[threadIdx.x >> 5] = s;
    __syncthreads();
    if (threadIdx.x < 8) {
        float v = red[threadIdx.x];
#pragma unroll
        for (int o = 4; o > 0; o >>= 1) v += __shfl_xor_sync(0xffu, v, o);
        if (threadIdx.x == 0) rs[row] = v;
    }
}

// ============================================================================
// tcgen05 PTX helpers (guarded)
// ============================================================================
#if HAVE_TCGEN05
#define MBAR_INIT(addr, cnt) \
    asm volatile("mbarrier.init.shared.b64 [%0], %1;" :: "r"(addr), "r"((uint32_t)(cnt)) : "memory")
#define MBAR_EXPECT(addr, bytes) \
    asm volatile("mbarrier.arrive.expect_tx.shared.b64 _, [%0], %1;" :: "r"(addr), "r"((uint32_t)(bytes)) : "memory")

__device__ __forceinline__ void mbar_wait(uint32_t addr, uint32_t parity) {
    uint32_t done;
    asm volatile(
        "{\n\t.reg .pred p;\n\t"
        "mbarrier.try_wait.parity.acquire.cta.shared::cta.b64 p, [%1], %2;\n\t"
        "selp.b32 %0, 1, 0, p;\n\t}"
        : "=r"(done) : "r"(addr), "r"(parity) : "memory");
    if (!done) {
        asm volatile(
            "{\n\t.reg .pred P1;\n\t"
            "WL_%=:\n\t"
            "mbarrier.try_wait.parity.acquire.cta.shared::cta.b64 P1, [%0], %1, 0x989680;\n\t"
            "@P1 bra.uni WD_%=;\n\t"
            "bra.uni WL_%=;\n\t"
            "WD_%=:\n\t}"
            :: "r"(addr), "r"(parity) : "memory");
    }
}

__device__ __forceinline__ void tma_ld_2d(uint32_t smem, const void* map, int x, int y, uint32_t mbar) {
    asm volatile(
        "cp.async.bulk.tensor.2d.shared::cta.global.tile.mbarrier::complete_tx::bytes "
        "[%0], [%1, {%2, %3}], [%4];"
        :: "r"(smem), "l"(map), "r"(x), "r"(y), "r"(mbar) : "memory");
}

// K-major SW64 smem descriptor: layout=4 (SW64), version=1, SBO=32, LBO=1
// (SW64 atom = 8 rows x 64B; rows here are 64B = KC(32) bf16)
__device__ __forceinline__ uint64_t mk_desc64(uint32_t addr) {
    const uint64_t BASE = (4ull << 61) | (1ull << 46) | (32ull << 32) | (1ull << 16);
    return BASE | ((uint64_t)(addr >> 4) & 0x3FFF);
}

__device__ __forceinline__ void mma_f16_ss_cg1(uint32_t d, uint64_t a, uint64_t b,
                                               uint32_t idesc, uint32_t en) {
    asm volatile(
        "{\n\t.reg .pred p;\n\t"
        "setp.ne.u32 p, %4, 0;\n\t"
        "tcgen05.mma.cta_group::1.kind::f16 [%0], %1, %2, %3, {%5, %5, %5, %5}, p;\n\t}"
        :: "r"(d), "l"(a), "l"(b), "r"(idesc), "r"(en), "r"(0u) : "memory");
}

__device__ __forceinline__ void tc_commit(uint32_t mbar) {
    asm volatile(
        "tcgen05.commit.cta_group::1.mbarrier::arrive::one.shared::cluster.b64 [%0];"
        :: "r"(mbar) : "memory");
}

#define TC_LD_X32(r, tmem_addr) \
    asm volatile( \
        "tcgen05.ld.sync.aligned.32x32b.x32.b32 " \
        "{%0, %1, %2, %3, %4, %5, %6, %7, " \
        " %8, %9, %10, %11, %12, %13, %14, %15, " \
        " %16, %17, %18, %19, %20, %21, %22, %23, " \
        " %24, %25, %26, %27, %28, %29, %30, %31}, [%32];" \
        : "=r"((r)[0]),  "=r"((r)[1]),  "=r"((r)[2]),  "=r"((r)[3]), \
          "=r"((r)[4]),  "=r"((r)[5]),  "=r"((r)[6]),  "=r"((r)[7]), \
          "=r"((r)[8]),  "=r"((r)[9]),  "=r"((r)[10]), "=r"((r)[11]), \
          "=r"((r)[12]), "=r"((r)[13]), "=r"((r)[14]), "=r"((r)[15]), \
          "=r"((r)[16]), "=r"((r)[17]), "=r"((r)[18]), "=r"((r)[19]), \
          "=r"((r)[20]), "=r"((r)[21]), "=r"((r)[22]), "=r"((r)[23]), \
          "=r"((r)[24]), "=r"((r)[25]), "=r"((r)[26]), "=r"((r)[27]), \
          "=r"((r)[28]), "=r"((r)[29]), "=r"((r)[30]), "=r"((r)[31]) \
        : "r"(tmem_addr))
#endif  // HAVE_TCGEN05

// ============================================================================
// Main GEMM kernel: one 128x512 output tile per CTA.
// ============================================================================
__global__ void __launch_bounds__(192, 1) qlinear_tc(
    const __grid_constant__ CUtensorMap tmAh,
    const __grid_constant__ CUtensorMap tmAl,
    const __grid_constant__ CUtensorMap tmB,
    const float* __restrict__ scales,
    const float* __restrict__ zps,
    const float* __restrict__ biasv,
    const float* __restrict__ rowsum,
    float* __restrict__ out)
{
#if HAVE_TCGEN05
    extern __shared__ __align__(1024) char smem[];
    const uint32_t sb = smem_u32(smem);
    const int tid  = threadIdx.x;
    const int wid  = tid >> 5;
    const int lane = tid & 31;
    const int cbase = blockIdx.x * BN;
    const int rbase = blockIdx.y * BM;
    const int nh = (cbase + BN <= OUT_F) ? 2 : 1;   // N=256 halves in this tile

    if (wid == 0) {
        asm volatile("tcgen05.alloc.cta_group::1.sync.aligned.shared::cta.b32 [%0], %1;"
                     :: "r"(sb + OFF_TMEM), "r"(512u) : "memory");
        asm volatile("tcgen05.relinquish_alloc_permit.cta_group::1.sync.aligned;");
    }
    if (tid == 0) {
        for (int s = 0; s < NST; s++) {
            MBAR_INIT(sb + OFF_FULL(s), 1);
            MBAR_INIT(sb + OFF_EMPTY(s), 1);
        }
        MBAR_INIT(sb + OFF_DONE, 1);
        asm volatile("fence.proxy.async.shared::cta;" ::: "memory");
    }
    __syncthreads();

    uint32_t tmem;
    asm volatile("ld.shared.b32 %0, [%1];" : "=r"(tmem) : "r"(sb + OFF_TMEM));

    // ---------------- producer warp (warp 4, lane 0) ----------------
    if (wid == 4 && lane == 0) {
        const uint32_t bytes = 16384u + (uint32_t)nh * 16384u;
        for (int c = 0; c < NCH; c++) {
            const int s = c & (NST - 1);
            if (c >= NST) mbar_wait(sb + OFF_EMPTY(s), ((c >> 2) - 1) & 1);
            MBAR_EXPECT(sb + OFF_FULL(s), bytes);
            const uint32_t st = sb + OFF_ST(s);
            tma_ld_2d(st + ST_AH, &tmAh, c * KC, rbase, sb + OFF_FULL(s));
            tma_ld_2d(st + ST_AL, &tmAl, c * KC, rbase, sb + OFF_FULL(s));
            tma_ld_2d(st + ST_B,  &tmB,  c * KC, cbase, sb + OFF_FULL(s));
            if (nh == 2)
                tma_ld_2d(st + ST_B + 16384, &tmB, c * KC, cbase + 256, sb + OFF_FULL(s));
        }
    }

    // ---------------- MMA driver warp (warp 5, lane 0) ----------------
    if (wid == 5 && lane == 0) {
        for (int c = 0; c < NCH; c++) {
            const int s = c & (NST - 1);
            mbar_wait(sb + OFF_FULL(s), (c >> 2) & 1);
            const uint32_t st = sb + OFF_ST(s);
            const uint64_t ah = mk_desc64(st + ST_AH);
            const uint64_t al = mk_desc64(st + ST_AL);
            const uint32_t en0 = (c > 0) ? 1u : 0u;
#pragma unroll
            for (int h = 0; h < 2; h++) {
                if (h >= nh) break;
                const uint64_t bd = mk_desc64(st + ST_B + h * 16384);
                const uint32_t D  = tmem + h * 256;
                // hi pass: 2 k-steps (K=16 each, +32B = +2 desc units)
                mma_f16_ss_cg1(D, ah,     bd,     MMA_IDESC, en0);
                mma_f16_ss_cg1(D, ah + 2, bd + 2, MMA_IDESC, 1u);
                // lo pass
                mma_f16_ss_cg1(D, al,     bd,     MMA_IDESC, 1u);
                mma_f16_ss_cg1(D, al + 2, bd + 2, MMA_IDESC, 1u);
            }
            tc_commit(sb + OFF_EMPTY(s));
            if (c == NCH - 1) tc_commit(sb + OFF_DONE);
        }
    }

    // ---------------- epilogue warps (warps 0-3, 128 threads) ----------------
    if (wid < 4) {
        // preload per-column params into SMEM while mainloop runs
        float* s_sc = (float*)(smem + OFF_PRM);
        float* s_zp = s_sc + BN;
        float* s_bi = s_zp + BN;
        const int ncols = nh * 256;
        for (int i = tid; i < ncols; i += 128) {
            s_sc[i] = scales[cbase + i];
            s_zp[i] = zps[cbase + i];
            s_bi[i] = biasv[cbase + i];
        }
        asm volatile("bar.sync 1, 128;" ::: "memory");   // order params among epi warps

        mbar_wait(sb + OFF_DONE, 0);
        asm volatile("tcgen05.fence::after_thread_sync;" ::: "memory");

        const int row = rbase + wid * 32 + lane;
        const float rs = rowsum[row];
        float* orow = out + (size_t)row * OUT_F + cbase;
        const int nblk = 8 * nh;
#pragma unroll 1
        for (int blk = 0; blk < nblk; blk++) {
            uint32_t r[32];
            TC_LD_X32(r, tmem + blk * 32);
            asm volatile("tcgen05.wait::ld.sync.aligned;" ::: "memory");
#pragma unroll
            for (int c = 0; c < 32; c += 4) {
                const int col = blk * 32 + c;
                float4 v;
                v.x = (__uint_as_float(r[c+0]) - s_zp[col+0] * rs) * s_sc[col+0] + s_bi[col+0];
                v.y = (__uint_as_float(r[c+1]) - s_zp[col+1] * rs) * s_sc[col+1] + s_bi[col+1];
                v.z = (__uint_as_float(r[c+2]) - s_zp[col+2] * rs) * s_sc[col+2] + s_bi[col+2];
                v.w = (__uint_as_float(r[c+3]) - s_zp[col+3] * rs) * s_sc[col+3] + s_bi[col+3];
                *reinterpret_cast<float4*>(orow + col) = v;
            }
        }
    }

    __syncthreads();
    if (wid == 0) {
        asm volatile("tcgen05.dealloc.cta_group::1.sync.aligned.b32 %0, %1;"
                     :: "r"(tmem), "r"(512u));
    }
#else
    (void)tmAh; (void)tmAl; (void)tmB; (void)scales; (void)zps; (void)biasv;
    (void)rowsum; (void)out;
#endif
}

// ============================================================================
// Host launcher
// ============================================================================
typedef CUresult (*tme_fn_t)(CUtensorMap*, CUtensorMapDataType, cuuint32_t, void*,
                             const cuuint64_t*, const cuuint64_t*,
                             const cuuint32_t*, const cuuint32_t*,
                             CUtensorMapInterleave, CUtensorMapSwizzle,
                             CUtensorMapL2promotion, CUtensorMapFloatOOBfill);

extern "C" void kernel_launch(void* const* d_in, const int* in_sizes, int n_in,
                              void* d_out, int out_size) {
    const float* input  = (const float*)d_in[0];
    const int*   w      = (const int*)d_in[1];
    const float* scales = (const float*)d_in[2];
    const float* zps    = (const float*)d_in[3];
    const float* bias   = (const float*)d_in[4];
    float* out = (float*)d_out;
    (void)in_sizes; (void)n_in; (void)out_size;

    void *pW = nullptr, *pAh = nullptr, *pAl = nullptr, *pRs = nullptr;
    cudaGetSymbolAddress(&pW,  g_W);
    cudaGetSymbolAddress(&pAh, g_Ahi);
    cudaGetSymbolAddress(&pAl, g_Alo);
    cudaGetSymbolAddress(&pRs, g_rowsum);

    tme_fn_t encode = nullptr;
    cudaDriverEntryPointQueryResult qr;
    cudaGetDriverEntryPoint("cuTensorMapEncodeTiled", (void**)&encode,
                            cudaEnableDefault, &qr);

    CUtensorMap mAh, mAl, mB;
    __builtin_memset(&mAh, 0, sizeof(mAh));
    __builtin_memset(&mAl, 0, sizeof(mAl));
    __builtin_memset(&mB, 0, sizeof(mB));
    if (encode) {
        {
            cuuint64_t dims[2]    = { IN_F, TOKENS };
            cuuint64_t strides[1] = { IN_F * sizeof(__nv_bfloat16) };
            cuuint32_t box[2]     = { KC, BM };        // 32 bf16 = 64B rows (SW64)
            cuuint32_t es[2]      = { 1, 1 };
            encode(&mAh, CU_TENSOR_MAP_DATA_TYPE_BFLOAT16, 2, pAh, dims, strides, box, es,
                   CU_TENSOR_MAP_INTERLEAVE_NONE, CU_TENSOR_MAP_SWIZZLE_64B,
                   CU_TENSOR_MAP_L2_PROMOTION_L2_128B, CU_TENSOR_MAP_FLOAT_OOB_FILL_NONE);
            encode(&mAl, CU_TENSOR_MAP_DATA_TYPE_BFLOAT16, 2, pAl, dims, strides, box, es,
                   CU_TENSOR_MAP_INTERLEAVE_NONE, CU_TENSOR_MAP_SWIZZLE_64B,
                   CU_TENSOR_MAP_L2_PROMOTION_L2_128B, CU_TENSOR_MAP_FLOAT_OOB_FILL_NONE);
        }
        {
            cuuint64_t dims[2]    = { IN_F, OUT_F };
            cuuint64_t strides[1] = { IN_F * sizeof(__nv_bfloat16) };
            cuuint32_t box[2]     = { KC, 256 };       // 256 rows per half-tile load
            cuuint32_t es[2]      = { 1, 1 };
            encode(&mB, CU_TENSOR_MAP_DATA_TYPE_BFLOAT16, 2, pW, dims, strides, box, es,
                   CU_TENSOR_MAP_INTERLEAVE_NONE, CU_TENSOR_MAP_SWIZZLE_64B,
                   CU_TENSOR_MAP_L2_PROMOTION_L2_128B, CU_TENSOR_MAP_FLOAT_OOB_FILL_NONE);
        }
    }

    cudaFuncSetAttribute(qlinear_tc, cudaFuncAttributeMaxDynamicSharedMemorySize,
                         SMEM_TOTAL);

    // preprocessing
    {
        int n4 = (OUT_F * IN_F) / 4;
        k_convert_w<<<(n4 + 255) / 256, 256>>>((const int4*)w, (uint2*)pW, n4);
    }
    {
        int n4 = (TOKENS * IN_F) / 4;
        k_convert_x<<<(n4 + 255) / 256, 256>>>((const float4*)input,
                                               (uint2*)pAh, (uint2*)pAl, n4);
    }
    k_rowsum<<<TOKENS, 256>>>(input, (float*)pRs);

    // GEMM: grid.x = ceil(11008/512) = 22 (last tile ragged: 256 cols), grid.y = 32
    dim3 grid((OUT_F + BN - 1) / BN, TOKENS / BM);
    qlinear_tc<<<grid, 192, SMEM_TOTAL>>>(mAh, mAl, mB, scales, zps, bias,
                                          (const float*)pRs, out);
}

// round 6
// speedup vs baseline: 1.2819x; 1.0813x over previous
#include <cuda_runtime.h>
#include <cuda.h>
#include <cuda_bf16.h>
#include <cstdint>
#include <cstdio>

// ============================================================================
// QuantizedLinear: out[t,o] = (sum_k x[t,k]*(w[o,k]-zp[o])) * scale[o] + bias[o]
//   M=TOKENS=4096, N=OUT_F=11008, K=IN_F=4096
//
// tcgen05 cg2 kernel: cluster(2,1,1) pairs compute M=256 x N=512 tiles.
// KC=32, SW64 swizzle, 6-stage cg2-TMA pipeline, warp-specialized:
//   warps 0-3 epilogue, warp 4 TMA producer (both CTAs), warp 5 MMA driver
//   (leader CTA only). B split N/2-rows-per-CTA per cg2 MMA semantics.
// Numerics: int8 W -> bf16 exact; input split hi+lo bf16; 2 GEMMs, fp32 acc.
// ============================================================================

#define TOKENS 4096
#define IN_F   4096
#define OUT_F  11008

#define BN  512                // N per pair-tile (two N=256 MMA regions)
#define KC  32
#define NCH (IN_F / KC)        // 128 chunks
#define NST 6                  // pipeline stages

#if defined(__CUDA_ARCH__) && (defined(__CUDA_ARCH_FEAT_SM100_ALL) || defined(__CUDA_ARCH_FEAT_SM103_ALL) || defined(__CUDA_ARCH_FEAT_SM101_ALL))
#define HAVE_TCGEN05 1
#else
#define HAVE_TCGEN05 0
#endif

// ---- dynamic SMEM layout (per CTA) ----
#define OFF_TMEM     0
#define OFF_FULL(s)  (16 + 8*(s))     // 16..56
#define OFF_EMPTY(s) (64 + 8*(s))     // 64..104
#define OFF_DONE     112
#define STAGE_STRIDE 32768            // AH 8K + AL 8K + B(h0) 8K + B(h1) 8K
#define OFF_ST(s)    (1024 + (s)*STAGE_STRIDE)
#define ST_AH        0
#define ST_AL        8192
#define ST_B         16384            // + h*8192
#define OFF_PRM      (1024 + NST*STAGE_STRIDE)   // 197632
#define SMEM_TOTAL   (OFF_PRM + 3*BN*4)          // 203776

// idesc kind::f16 cg2: dtype=F32(bit4), atype=BF16(bit7), btype=BF16(bit10),
// N/8 at [17:22] (N=256 per MMA region), M_total/16 at [24:28] (M=256)
#define MMA_IDESC ((1u<<4) | (1u<<7) | (1u<<10) | ((256/8)<<17) | ((256/16)<<24))

// ---- scratch (device globals: no allocation allowed) ----
__device__ __align__(1024) __nv_bfloat16 g_W  [(size_t)OUT_F  * IN_F];
__device__ __align__(1024) __nv_bfloat16 g_Ahi[(size_t)TOKENS * IN_F];
__device__ __align__(1024) __nv_bfloat16 g_Alo[(size_t)TOKENS * IN_F];
__device__ float g_rowsum[TOKENS];

// ============================================================================
// Common helpers
// ============================================================================
__device__ __forceinline__ uint32_t smem_u32(const void* p) {
    uint32_t a;
    asm("{ .reg .u64 t; cvta.to.shared.u64 t, %1; cvt.u32.u64 %0, t; }"
        : "=r"(a) : "l"(p));
    return a;
}

// ============================================================================
// Preprocessing kernels
// ============================================================================
__global__ void k_convert_w(const int4* __restrict__ w4, uint2* __restrict__ W, int n4) {
    int i = blockIdx.x * blockDim.x + threadIdx.x;
    if (i >= n4) return;
    int4 v = w4[i];
    union { __nv_bfloat16 h[4]; uint2 u; } o;
    o.h[0] = __float2bfloat16((float)v.x);   // |w|<=128: exact in bf16
    o.h[1] = __float2bfloat16((float)v.y);
    o.h[2] = __float2bfloat16((float)v.z);
    o.h[3] = __float2bfloat16((float)v.w);
    W[i] = o.u;
}

// fused: hi/lo split + per-row sum (one block per token row)
__global__ void k_convert_x(const float4* __restrict__ x4, uint2* __restrict__ hi,
                            uint2* __restrict__ lo, float* __restrict__ rs) {
    const int row = blockIdx.x;
    const float4* px = x4 + (size_t)row * (IN_F / 4);
    uint2* ph = hi + (size_t)row * (IN_F / 4);
    uint2* pl = lo + (size_t)row * (IN_F / 4);
    float s = 0.f;
    for (int i = threadIdx.x; i < IN_F / 4; i += 256) {
        float4 v = px[i];
        union { __nv_bfloat16 h[4]; uint2 u; } H, L;
        const float* f = &v.x;
#pragma unroll
        for (int j = 0; j < 4; j++) {
            __nv_bfloat16 h = __float2bfloat16(f[j]);
            H.h[j] = h;
            L.h[j] = __float2bfloat16(f[j] - __bfloat162float(h));
            s += f[j];
        }
        ph[i] = H.u;
        pl[i] = L.u;
    }
#pragma unroll
    for (int o = 16; o > 0; o >>= 1) s += __shfl_xor_sync(0xffffffffu, s, o);
    __shared__ float red[8];
    if ((threadIdx.x & 31) == 0) red[threadIdx.x >> 5] = s;
    __syncthreads();
    if (threadIdx.x < 8) {
        float v = red[threadIdx.x];
#pragma unroll
        for (int o = 4; o > 0; o >>= 1) v += __shfl_xor_sync(0xffu, v, o);
        if (threadIdx.x == 0) rs[row] = v;
    }
}

// ============================================================================
// tcgen05 PTX helpers (guarded)
// ============================================================================
#if HAVE_TCGEN05
#define MBAR_INIT(addr, cnt) \
    asm volatile("mbarrier.init.shared.b64 [%0], %1;" :: "r"(addr), "r"((uint32_t)(cnt)) : "memory")
#define MBAR_EXPECT(addr, bytes) \
    asm volatile("mbarrier.arrive.expect_tx.shared.b64 _, [%0], %1;" :: "r"(addr), "r"((uint32_t)(bytes)) : "memory")

__device__ __forceinline__ void mbar_wait(uint32_t addr, uint32_t parity) {
    uint32_t done;
    asm volatile(
        "{\n\t.reg .pred p;\n\t"
        "mbarrier.try_wait.parity.acquire.cta.shared::cta.b64 p, [%1], %2;\n\t"
        "selp.b32 %0, 1, 0, p;\n\t}"
        : "=r"(done) : "r"(addr), "r"(parity) : "memory");
    if (!done) {
        asm volatile(
            "{\n\t.reg .pred P1;\n\t"
            "WL_%=:\n\t"
            "mbarrier.try_wait.parity.acquire.cta.shared::cta.b64 P1, [%0], %1, 0x989680;\n\t"
            "@P1 bra.uni WD_%=;\n\t"
            "bra.uni WL_%=;\n\t"
            "WD_%=:\n\t}"
            :: "r"(addr), "r"(parity) : "memory");
    }
}

// cg2 TMA 3D load: both CTAs execute; complete_tx targets leader CTA's barrier
// via Sm100MmaPeerBitMask (clear bit 24 of the local barrier address).
__device__ __forceinline__ void tma_ld_cg2(uint32_t smem, const void* map,
                                           int x, int y, uint32_t mbar) {
    asm volatile(
        "{\n\t.reg .b32 lb;\n\t"
        "and.b32 lb, %5, 0xFEFFFFFF;\n\t"
        "cp.async.bulk.tensor.3d.cta_group::2.shared::cluster.global"
        ".tile.mbarrier::complete_tx::bytes [%0], [%1, {%2, %3, %4}], [lb];\n\t}"
        :: "r"(smem), "l"(map), "r"(x), "r"(y), "r"(0), "r"(mbar) : "memory");
}

// K-major SW64 smem descriptor: layout=4 (SW64), version=1, SBO=32, LBO=1
__device__ __forceinline__ uint64_t mk_desc64(uint32_t addr) {
    const uint64_t BASE = (4ull << 61) | (1ull << 46) | (32ull << 32) | (1ull << 16);
    return BASE | ((uint64_t)(addr >> 4) & 0x3FFF);
}

__device__ __forceinline__ void mma_f16_ss_cg2(uint32_t d, uint64_t a, uint64_t b,
                                               uint32_t idesc, uint32_t en) {
    asm volatile(
        "{\n\t.reg .pred p;\n\t"
        "setp.ne.u32 p, %4, 0;\n\t"
        "tcgen05.mma.cta_group::2.kind::f16 [%0], %1, %2, %3, "
        "{%5, %5, %5, %5, %5, %5, %5, %5}, p;\n\t}"
        :: "r"(d), "l"(a), "l"(b), "r"(idesc), "r"(en), "r"(0u) : "memory");
}

__device__ __forceinline__ void tc_commit_mc2(uint32_t mbar) {
    asm volatile(
        "tcgen05.commit.cta_group::2.mbarrier::arrive::one.shared::cluster"
        ".multicast::cluster.b64 [%0], %1;"
        :: "r"(mbar), "h"((uint16_t)0x3) : "memory");
}

#define TC_LD_X32(r, tmem_addr) \
    asm volatile( \
        "tcgen05.ld.sync.aligned.32x32b.x32.b32 " \
        "{%0, %1, %2, %3, %4, %5, %6, %7, " \
        " %8, %9, %10, %11, %12, %13, %14, %15, " \
        " %16, %17, %18, %19, %20, %21, %22, %23, " \
        " %24, %25, %26, %27, %28, %29, %30, %31}, [%32];" \
        : "=r"((r)[0]),  "=r"((r)[1]),  "=r"((r)[2]),  "=r"((r)[3]), \
          "=r"((r)[4]),  "=r"((r)[5]),  "=r"((r)[6]),  "=r"((r)[7]), \
          "=r"((r)[8]),  "=r"((r)[9]),  "=r"((r)[10]), "=r"((r)[11]), \
          "=r"((r)[12]), "=r"((r)[13]), "=r"((r)[14]), "=r"((r)[15]), \
          "=r"((r)[16]), "=r"((r)[17]), "=r"((r)[18]), "=r"((r)[19]), \
          "=r"((r)[20]), "=r"((r)[21]), "=r"((r)[22]), "=r"((r)[23]), \
          "=r"((r)[24]), "=r"((r)[25]), "=r"((r)[26]), "=r"((r)[27]), \
          "=r"((r)[28]), "=r"((r)[29]), "=r"((r)[30]), "=r"((r)[31]) \
        : "r"(tmem_addr))

#define CLUSTER_SYNC_() do { \
    asm volatile("barrier.cluster.arrive.aligned;" ::: "memory"); \
    asm volatile("barrier.cluster.wait.aligned;" ::: "memory"); \
} while (0)
#endif  // HAVE_TCGEN05

// ============================================================================
// Main GEMM kernel: cluster pair computes a 256x512 output tile.
//   grid.x = M CTAs (32, cluster-paired), grid.y = N tiles (22)
// ============================================================================
__global__ void __launch_bounds__(192, 1) __cluster_dims__(2, 1, 1) qlinear_tc(
    const __grid_constant__ CUtensorMap tmAh,
    const __grid_constant__ CUtensorMap tmAl,
    const __grid_constant__ CUtensorMap tmB,
    const float* __restrict__ scales,
    const float* __restrict__ zps,
    const float* __restrict__ biasv,
    const float* __restrict__ rowsum,
    float* __restrict__ out)
{
#if HAVE_TCGEN05
    extern __shared__ __align__(1024) char smem[];
    const uint32_t sb = smem_u32(smem);
    const int tid  = threadIdx.x;
    const int wid  = tid >> 5;
    const int lane = tid & 31;
    const int rank  = blockIdx.x & 1;          // cg2 pair rank
    const int rbase = blockIdx.x * 128;        // this CTA's 128 output rows
    const int cbase = blockIdx.y * BN;
    const int nh = (cbase + BN <= OUT_F) ? 2 : 1;  // live N=256 regions

    if (wid == 0) {
        asm volatile("tcgen05.alloc.cta_group::2.sync.aligned.shared::cta.b32 [%0], %1;"
                     :: "r"(sb + OFF_TMEM), "r"(512u) : "memory");
        asm volatile("tcgen05.relinquish_alloc_permit.cta_group::2.sync.aligned;");
    }
    if (tid == 0) {
        for (int s = 0; s < NST; s++) {
            MBAR_INIT(sb + OFF_FULL(s), 1);
            MBAR_INIT(sb + OFF_EMPTY(s), 1);
        }
        MBAR_INIT(sb + OFF_DONE, 1);
        asm volatile("fence.proxy.async.shared::cta;" ::: "memory");
    }
    __syncthreads();
    CLUSTER_SYNC_();   // peer barriers must be live before cg2 TMA / commits

    uint32_t tmem;
    asm volatile("ld.shared.b32 %0, [%1];" : "=r"(tmem) : "r"(sb + OFF_TMEM));

    // ---------------- producer warp (warp 4, lane 0, BOTH CTAs) ----------------
    if (wid == 4 && lane == 0) {
        // pair total bytes per stage: 2 CTAs x (AH 8K + AL 8K + B nh*8K)
        const uint32_t pair_bytes = 2u * (16384u + (uint32_t)nh * 8192u);
        int s = 0, k = 0;
        for (int c = 0; c < NCH; c++) {
            if (k > 0) mbar_wait(sb + OFF_EMPTY(s), (k - 1) & 1);
            if (rank == 0) MBAR_EXPECT(sb + OFF_FULL(s), pair_bytes);
            const uint32_t st = sb + OFF_ST(s);
            const uint32_t fb = sb + OFF_FULL(s);
            tma_ld_cg2(st + ST_AH, &tmAh, c * KC, rbase, fb);
            tma_ld_cg2(st + ST_AL, &tmAl, c * KC, rbase, fb);
            // B: this CTA holds its 128-row half of each N=256 region
            tma_ld_cg2(st + ST_B, &tmB, c * KC, cbase + rank * 128, fb);
            if (nh == 2)
                tma_ld_cg2(st + ST_B + 8192, &tmB, c * KC, cbase + 256 + rank * 128, fb);
            if (++s == NST) { s = 0; k++; }
        }
    }

    // ---------------- MMA driver (leader CTA, warp 5, lane 0) ----------------
    if (rank == 0 && wid == 5 && lane == 0) {
        int s = 0, k = 0;
        for (int c = 0; c < NCH; c++) {
            mbar_wait(sb + OFF_FULL(s), k & 1);
            const uint32_t st = sb + OFF_ST(s);
            const uint64_t ah = mk_desc64(st + ST_AH);
            const uint64_t al = mk_desc64(st + ST_AL);
            const uint32_t en0 = (c > 0) ? 1u : 0u;
#pragma unroll
            for (int h = 0; h < 2; h++) {
                if (h >= nh) break;
                const uint64_t bd = mk_desc64(st + ST_B + h * 8192);
                const uint32_t D  = tmem + h * 256;
                mma_f16_ss_cg2(D, ah,     bd,     MMA_IDESC, en0);
                mma_f16_ss_cg2(D, ah + 2, bd + 2, MMA_IDESC, 1u);
                mma_f16_ss_cg2(D, al,     bd,     MMA_IDESC, 1u);
                mma_f16_ss_cg2(D, al + 2, bd + 2, MMA_IDESC, 1u);
            }
            tc_commit_mc2(sb + OFF_EMPTY(s));
            if (c == NCH - 1) tc_commit_mc2(sb + OFF_DONE);
            if (++s == NST) { s = 0; k++; }
        }
    }

    // ---------------- epilogue warps (warps 0-3, BOTH CTAs) ----------------
    if (wid < 4) {
        float* s_sc = (float*)(smem + OFF_PRM);
        float* s_zp = s_sc + BN;
        float* s_bi = s_zp + BN;
        const int ncols = nh * 256;
        for (int i = tid; i < ncols; i += 128) {
            s_sc[i] = scales[cbase + i];
            s_zp[i] = zps[cbase + i];
            s_bi[i] = biasv[cbase + i];
        }
        asm volatile("bar.sync 1, 128;" ::: "memory");

        mbar_wait(sb + OFF_DONE, 0);
        asm volatile("tcgen05.fence::after_thread_sync;" ::: "memory");

        const int row = rbase + wid * 32 + lane;   // this CTA's TMEM lanes
        const float rs = rowsum[row];
        float* orow = out + (size_t)row * OUT_F + cbase;
        const int nblk = 8 * nh;
#pragma unroll 1
        for (int blk = 0; blk < nblk; blk++) {
            uint32_t r[32];
            TC_LD_X32(r, tmem + blk * 32);
            asm volatile("tcgen05.wait::ld.sync.aligned;" ::: "memory");
#pragma unroll
            for (int c = 0; c < 32; c += 4) {
                const int col = blk * 32 + c;
                float4 v;
                v.x = (__uint_as_float(r[c+0]) - s_zp[col+0] * rs) * s_sc[col+0] + s_bi[col+0];
                v.y = (__uint_as_float(r[c+1]) - s_zp[col+1] * rs) * s_sc[col+1] + s_bi[col+1];
                v.z = (__uint_as_float(r[c+2]) - s_zp[col+2] * rs) * s_sc[col+2] + s_bi[col+2];
                v.w = (__uint_as_float(r[c+3]) - s_zp[col+3] * rs) * s_sc[col+3] + s_bi[col+3];
                *reinterpret_cast<float4*>(orow + col) = v;
            }
        }
    }

    __syncthreads();
    CLUSTER_SYNC_();   // both CTAs done with TMEM before collective dealloc
    if (wid == 0) {
        asm volatile("tcgen05.dealloc.cta_group::2.sync.aligned.b32 %0, %1;"
                     :: "r"(tmem), "r"(512u));
    }
    CLUSTER_SYNC_();
#else
    (void)tmAh; (void)tmAl; (void)tmB; (void)scales; (void)zps; (void)biasv;
    (void)rowsum; (void)out;
#endif
}

// ============================================================================
// Host launcher
// ============================================================================
typedef CUresult (*tme_fn_t)(CUtensorMap*, CUtensorMapDataType, cuuint32_t, void*,
                             const cuuint64_t*, const cuuint64_t*,
                             const cuuint32_t*, const cuuint32_t*,
                             CUtensorMapInterleave, CUtensorMapSwizzle,
                             CUtensorMapL2promotion, CUtensorMapFloatOOBfill);

extern "C" void kernel_launch(void* const* d_in, const int* in_sizes, int n_in,
                              void* d_out, int out_size) {
    const float* input  = (const float*)d_in[0];
    const int*   w      = (const int*)d_in[1];
    const float* scales = (const float*)d_in[2];
    const float* zps    = (const float*)d_in[3];
    const float* bias   = (const float*)d_in[4];
    float* out = (float*)d_out;
    (void)in_sizes; (void)n_in; (void)out_size;

    void *pW = nullptr, *pAh = nullptr, *pAl = nullptr, *pRs = nullptr;
    cudaGetSymbolAddress(&pW,  g_W);
    cudaGetSymbolAddress(&pAh, g_Ahi);
    cudaGetSymbolAddress(&pAl, g_Alo);
    cudaGetSymbolAddress(&pRs, g_rowsum);

    tme_fn_t encode = nullptr;
    cudaDriverEntryPointQueryResult qr;
    cudaGetDriverEntryPoint("cuTensorMapEncodeTiled", (void**)&encode,
                            cudaEnableDefault, &qr);

    CUtensorMap mAh, mAl, mB;
    __builtin_memset(&mAh, 0, sizeof(mAh));
    __builtin_memset(&mAl, 0, sizeof(mAl));
    __builtin_memset(&mB, 0, sizeof(mB));
    if (encode) {
        {
            cuuint64_t dims[3]    = { IN_F, TOKENS, 1 };
            cuuint64_t strides[2] = { IN_F * sizeof(__nv_bfloat16),
                                      (cuuint64_t)IN_F * TOKENS * sizeof(__nv_bfloat16) };
            cuuint32_t box[3]     = { KC, 128, 1 };    // 32 bf16 = 64B rows (SW64)
            cuuint32_t es[3]      = { 1, 1, 1 };
            encode(&mAh, CU_TENSOR_MAP_DATA_TYPE_BFLOAT16, 3, pAh, dims, strides, box, es,
                   CU_TENSOR_MAP_INTERLEAVE_NONE, CU_TENSOR_MAP_SWIZZLE_64B,
                   CU_TENSOR_MAP_L2_PROMOTION_L2_128B, CU_TENSOR_MAP_FLOAT_OOB_FILL_NONE);
            encode(&mAl, CU_TENSOR_MAP_DATA_TYPE_BFLOAT16, 3, pAl, dims, strides, box, es,
                   CU_TENSOR_MAP_INTERLEAVE_NONE, CU_TENSOR_MAP_SWIZZLE_64B,
                   CU_TENSOR_MAP_L2_PROMOTION_L2_128B, CU_TENSOR_MAP_FLOAT_OOB_FILL_NONE);
        }
        {
            cuuint64_t dims[3]    = { IN_F, OUT_F, 1 };
            cuuint64_t strides[2] = { IN_F * sizeof(__nv_bfloat16),
                                      (cuuint64_t)IN_F * OUT_F * sizeof(__nv_bfloat16) };
            cuuint32_t box[3]     = { KC, 128, 1 };    // 128-row pieces per CTA
            cuuint32_t es[3]      = { 1, 1, 1 };
            encode(&mB, CU_TENSOR_MAP_DATA_TYPE_BFLOAT16, 3, pW, dims, strides, box, es,
                   CU_TENSOR_MAP_INTERLEAVE_NONE, CU_TENSOR_MAP_SWIZZLE_64B,
                   CU_TENSOR_MAP_L2_PROMOTION_L2_128B, CU_TENSOR_MAP_FLOAT_OOB_FILL_NONE);
        }
    }

    cudaFuncSetAttribute(qlinear_tc, cudaFuncAttributeMaxDynamicSharedMemorySize,
                         SMEM_TOTAL);

    // preprocessing
    {
        int n4 = (OUT_F * IN_F) / 4;
        k_convert_w<<<(n4 + 255) / 256, 256>>>((const int4*)w, (uint2*)pW, n4);
    }
    k_convert_x<<<TOKENS, 256>>>((const float4*)input, (uint2*)pAh, (uint2*)pAl,
                                 (float*)pRs);

    // GEMM: grid.x = 32 M-CTAs (cg2 pairs), grid.y = 22 N tiles (last ragged)
    dim3 grid(TOKENS / 128, (OUT_F + BN - 1) / BN);
    qlinear_tc<<<grid, 192, SMEM_TOTAL>>>(mAh, mAl, mB, scales, zps, bias,
                                          (const float*)pRs, out);
}

// round 9
// speedup vs baseline: 1.8869x; 1.4719x over previous
#include <cuda_runtime.h>
#include <cuda.h>
#include <cuda_bf16.h>
#include <cstdint>
#include <cstdio>

// ============================================================================
// QuantizedLinear via two-digit int8 tcgen05 GEMM.
//   out[t,o] = (sum_k x[t,k]*(w[o,k]-zp[o])) * scale[o] + bias[o]
//   M=TOKENS=4096, N=OUT_F=11008, K=IN_F=4096
//
// W is int8-exact (given int32 in [-128,127] -> s8 pack).
// x fixed-point per row: x ~= s_row*(128*h + l), h,l in s8 (|v|<=16000).
// Two kind::i8 GEMMs (s32 accum in TMEM): D1 = h.W^T, D0 = l.W^T.
// out = (s_row*(128*D1 + D0) - zp*rowsum)*scale + bias  (rowsum exact fp32).
//
// cg2 cluster(2,1,1): pair computes 256x256 tile. KC=64, SW64, 7-stage TMA
// pipeline. Warps: 0-3 epilogue, 4 producer (both CTAs), 5 MMA driver (leader).
// ============================================================================

#define TOKENS 4096
#define IN_F   4096
#define OUT_F  11008

#define BN  256                 // N per pair-tile (one N=256 MMA region)
#define KC  64
#define NCH (IN_F / KC)         // 64 chunks
#define NST 7                   // pipeline stages

#if defined(__CUDA_ARCH__) && (defined(__CUDA_ARCH_FEAT_SM100_ALL) || defined(__CUDA_ARCH_FEAT_SM103_ALL) || defined(__CUDA_ARCH_FEAT_SM101_ALL))
#define HAVE_TCGEN05 1
#else
#define HAVE_TCGEN05 0
#endif

// ---- dynamic SMEM layout (per CTA) ----
#define OFF_TMEM     0
#define OFF_FULL(s)  (16 + 8*(s))     // 7 stages: 16..64
#define OFF_EMPTY(s) (80 + 8*(s))     // 80..128
#define OFF_DONE     144
#define STAGE_STRIDE 24576            // AH 8K + AL 8K + B 8K (int8)
#define OFF_ST(s)    (1024 + (s)*STAGE_STRIDE)
#define ST_AH        0
#define ST_AL        8192
#define ST_B         16384
#define OFF_PRM      (1024 + NST*STAGE_STRIDE)   // 173056
#define SMEM_TOTAL   (OFF_PRM + 3*BN*4)          // 176128

// idesc kind::i8 cg2: c_format=S32(2) at [4:6), a_format=S8(1) at [7:10),
// b_format=S8(1) at [10:13), N/8 at [17:23), M_total/16 at [24:29)
#define MMA_IDESC ((2u<<4) | (1u<<7) | (1u<<10) | ((BN/8)<<17) | ((256/16)<<24))

// ---- scratch (device globals: no allocation allowed) ----
__device__ __align__(1024) int8_t g_W8[(size_t)OUT_F  * IN_F];
__device__ __align__(1024) int8_t g_Ah[(size_t)TOKENS * IN_F];
__device__ __align__(1024) int8_t g_Al[(size_t)TOKENS * IN_F];
__device__ float g_rowsum[TOKENS];
__device__ float g_rscale[TOKENS];

// ============================================================================
// Common helpers
// ============================================================================
__device__ __forceinline__ uint32_t smem_u32(const void* p) {
    uint32_t a;
    asm("{ .reg .u64 t; cvta.to.shared.u64 t, %1; cvt.u32.u64 %0, t; }"
        : "=r"(a) : "l"(p));
    return a;
}

// ============================================================================
// Preprocessing kernels
// ============================================================================
__global__ void k_pack_w(const int4* __restrict__ w4, char4* __restrict__ W, int n4) {
    int i = blockIdx.x * blockDim.x + threadIdx.x;
    if (i >= n4) return;
    int4 v = w4[i];
    W[i] = make_char4((signed char)v.x, (signed char)v.y,
                      (signed char)v.z, (signed char)v.w);
}

// per token row: rowmax/rowsum reduce, then two-digit int8 quantization
__global__ void k_convert_x(const float4* __restrict__ x4,
                            char4* __restrict__ hi, char4* __restrict__ lo,
                            float* __restrict__ rs, float* __restrict__ rsc) {
    const int row = blockIdx.x;
    const int tid = threadIdx.x;
    const float4* px = x4 + (size_t)row * (IN_F / 4);
    float mx = 0.f, sm = 0.f;
    for (int i = tid; i < IN_F / 4; i += 256) {
        float4 v = px[i];
        mx = fmaxf(mx, fmaxf(fmaxf(fabsf(v.x), fabsf(v.y)),
                             fmaxf(fabsf(v.z), fabsf(v.w))));
        sm += v.x + v.y + v.z + v.w;
    }
#pragma unroll
    for (int o = 16; o > 0; o >>= 1) {
        mx = fmaxf(mx, __shfl_xor_sync(0xffffffffu, mx, o));
        sm += __shfl_xor_sync(0xffffffffu, sm, o);
    }
    __shared__ float redM[8], redS[8], bc[2];
    if ((tid & 31) == 0) { redM[tid >> 5] = mx; redS[tid >> 5] = sm; }
    __syncthreads();
    if (tid < 8) {
        float m = redM[tid], s = redS[tid];
#pragma unroll
        for (int o = 4; o > 0; o >>= 1) {
            m = fmaxf(m, __shfl_xor_sync(0xffu, m, o));
            s += __shfl_xor_sync(0xffu, s, o);
        }
        if (tid == 0) {
            float scl = (m > 1e-30f) ? (m / 16000.f) : 0.f;
            bc[0] = (m > 1e-30f) ? (16000.f / m) : 0.f;   // inv scale
            bc[1] = s;
            rs[row]  = s;
            rsc[row] = scl;
        }
    }
    __syncthreads();
    const float inv = bc[0];
    char4* ph = hi + (size_t)row * (IN_F / 4);
    char4* pl = lo + (size_t)row * (IN_F / 4);
    for (int i = tid; i < IN_F / 4; i += 256) {
        float4 v = px[i];
        const float* f = &v.x;
        signed char hd[4], ld[4];
#pragma unroll
        for (int j = 0; j < 4; j++) {
            int vq = __float2int_rn(f[j] * inv);     // |vq| <= 16000
            int h  = (vq + 64) >> 7;                 // floor((vq+64)/128), |h|<=126
            int l  = vq - (h << 7);                  // in [-64, 63]
            hd[j] = (signed char)h;
            ld[j] = (signed char)l;
        }
        ph[i] = make_char4(hd[0], hd[1], hd[2], hd[3]);
        pl[i] = make_char4(ld[0], ld[1], ld[2], ld[3]);
    }
}

// ============================================================================
// tcgen05 PTX helpers (guarded)
// ============================================================================
#if HAVE_TCGEN05
#define MBAR_INIT(addr, cnt) \
    asm volatile("mbarrier.init.shared.b64 [%0], %1;" :: "r"(addr), "r"((uint32_t)(cnt)) : "memory")
#define MBAR_EXPECT(addr, bytes) \
    asm volatile("mbarrier.arrive.expect_tx.shared.b64 _, [%0], %1;" :: "r"(addr), "r"((uint32_t)(bytes)) : "memory")

__device__ __forceinline__ void mbar_wait(uint32_t addr, uint32_t parity) {
    uint32_t done;
    asm volatile(
        "{\n\t.reg .pred p;\n\t"
        "mbarrier.try_wait.parity.acquire.cta.shared::cta.b64 p, [%1], %2;\n\t"
        "selp.b32 %0, 1, 0, p;\n\t}"
        : "=r"(done) : "r"(addr), "r"(parity) : "memory");
    if (!done) {
        asm volatile(
            "{\n\t.reg .pred P1;\n\t"
            "WL_%=:\n\t"
            "mbarrier.try_wait.parity.acquire.cta.shared::cta.b64 P1, [%0], %1, 0x989680;\n\t"
            "@P1 bra.uni WD_%=;\n\t"
            "bra.uni WL_%=;\n\t"
            "WD_%=:\n\t}"
            :: "r"(addr), "r"(parity) : "memory");
    }
}

// cg2 TMA 3D load: both CTAs execute; complete_tx targets leader CTA's barrier
// via Sm100MmaPeerBitMask (clear bit 24 of the local barrier address).
__device__ __forceinline__ void tma_ld_cg2(uint32_t smem, const void* map,
                                           int x, int y, uint32_t mbar) {
    asm volatile(
        "{\n\t.reg .b32 lb;\n\t"
        "and.b32 lb, %5, 0xFEFFFFFF;\n\t"
        "cp.async.bulk.tensor.3d.cta_group::2.shared::cluster.global"
        ".tile.mbarrier::complete_tx::bytes [%0], [%1, {%2, %3, %4}], [lb];\n\t}"
        :: "r"(smem), "l"(map), "r"(x), "r"(y), "r"(0), "r"(mbar) : "memory");
}

// K-major SW64 smem descriptor: layout=4 (SW64), version=1, SBO=32, LBO=1
// (SW64 atom = 8 rows x 64B; rows here are 64B = KC(64) int8)
__device__ __forceinline__ uint64_t mk_desc64(uint32_t addr) {
    const uint64_t BASE = (4ull << 61) | (1ull << 46) | (32ull << 32) | (1ull << 16);
    return BASE | ((uint64_t)(addr >> 4) & 0x3FFF);
}

__device__ __forceinline__ void mma_i8_ss_cg2(uint32_t d, uint64_t a, uint64_t b,
                                              uint32_t idesc, uint32_t en) {
    asm volatile(
        "{\n\t.reg .pred p;\n\t"
        "setp.ne.u32 p, %4, 0;\n\t"
        "tcgen05.mma.cta_group::2.kind::i8 [%0], %1, %2, %3, "
        "{%5, %5, %5, %5, %5, %5, %5, %5}, p;\n\t}"
        :: "r"(d), "l"(a), "l"(b), "r"(idesc), "r"(en), "r"(0u) : "memory");
}

__device__ __forceinline__ void tc_commit_mc2(uint32_t mbar) {
    asm volatile(
        "tcgen05.commit.cta_group::2.mbarrier::arrive::one.shared::cluster"
        ".multicast::cluster.b64 [%0], %1;"
        :: "r"(mbar), "h"((uint16_t)0x3) : "memory");
}

#define TC_LD_X32(r, tmem_addr) \
    asm volatile( \
        "tcgen05.ld.sync.aligned.32x32b.x32.b32 " \
        "{%0, %1, %2, %3, %4, %5, %6, %7, " \
        " %8, %9, %10, %11, %12, %13, %14, %15, " \
        " %16, %17, %18, %19, %20, %21, %22, %23, " \
        " %24, %25, %26, %27, %28, %29, %30, %31}, [%32];" \
        : "=r"((r)[0]),  "=r"((r)[1]),  "=r"((r)[2]),  "=r"((r)[3]), \
          "=r"((r)[4]),  "=r"((r)[5]),  "=r"((r)[6]),  "=r"((r)[7]), \
          "=r"((r)[8]),  "=r"((r)[9]),  "=r"((r)[10]), "=r"((r)[11]), \
          "=r"((r)[12]), "=r"((r)[13]), "=r"((r)[14]), "=r"((r)[15]), \
          "=r"((r)[16]), "=r"((r)[17]), "=r"((r)[18]), "=r"((r)[19]), \
          "=r"((r)[20]), "=r"((r)[21]), "=r"((r)[22]), "=r"((r)[23]), \
          "=r"((r)[24]), "=r"((r)[25]), "=r"((r)[26]), "=r"((r)[27]), \
          "=r"((r)[28]), "=r"((r)[29]), "=r"((r)[30]), "=r"((r)[31]) \
        : "r"(tmem_addr))

#define CLUSTER_SYNC_() do { \
    asm volatile("barrier.cluster.arrive.aligned;" ::: "memory"); \
    asm volatile("barrier.cluster.wait.aligned;" ::: "memory"); \
} while (0)
#endif  // HAVE_TCGEN05

// ============================================================================
// Main GEMM kernel: cluster pair computes a 256x256 output tile.
//   grid.x = 32 M-CTAs (cluster-paired), grid.y = 43 N tiles (exact)
// ============================================================================
__global__ void __launch_bounds__(192, 1) __cluster_dims__(2, 1, 1) qlinear_tc(
    const __grid_constant__ CUtensorMap tmAh,
    const __grid_constant__ CUtensorMap tmAl,
    const __grid_constant__ CUtensorMap tmB,
    const float* __restrict__ scales,
    const float* __restrict__ zps,
    const float* __restrict__ biasv,
    const float* __restrict__ rowsum,
    const float* __restrict__ rscale,
    float* __restrict__ out)
{
#if HAVE_TCGEN05
    extern __shared__ __align__(1024) char smem[];
    const uint32_t sb = smem_u32(smem);
    const int tid  = threadIdx.x;
    const int wid  = tid >> 5;
    const int lane = tid & 31;
    const int rank  = blockIdx.x & 1;          // cg2 pair rank
    const int rbase = blockIdx.x * 128;        // this CTA's 128 output rows
    const int cbase = blockIdx.y * BN;

    if (wid == 0) {
        asm volatile("tcgen05.alloc.cta_group::2.sync.aligned.shared::cta.b32 [%0], %1;"
                     :: "r"(sb + OFF_TMEM), "r"(512u) : "memory");
        asm volatile("tcgen05.relinquish_alloc_permit.cta_group::2.sync.aligned;");
    }
    if (tid == 0) {
        for (int s = 0; s < NST; s++) {
            MBAR_INIT(sb + OFF_FULL(s), 1);
            MBAR_INIT(sb + OFF_EMPTY(s), 1);
        }
        MBAR_INIT(sb + OFF_DONE, 1);
        asm volatile("fence.proxy.async.shared::cta;" ::: "memory");
    }
    __syncthreads();
    CLUSTER_SYNC_();   // peer barriers must be live before cg2 TMA / commits

    uint32_t tmem;
    asm volatile("ld.shared.b32 %0, [%1];" : "=r"(tmem) : "r"(sb + OFF_TMEM));

    // ---------------- producer warp (warp 4, lane 0, BOTH CTAs) ----------------
    if (wid == 4 && lane == 0) {
        const uint32_t pair_bytes = 2u * STAGE_STRIDE;   // 49152
        int s = 0, k = 0;
        for (int c = 0; c < NCH; c++) {
            if (k > 0) mbar_wait(sb + OFF_EMPTY(s), (k - 1) & 1);
            if (rank == 0) MBAR_EXPECT(sb + OFF_FULL(s), pair_bytes);
            const uint32_t st = sb + OFF_ST(s);
            const uint32_t fb = sb + OFF_FULL(s);
            tma_ld_cg2(st + ST_AH, &tmAh, c * KC, rbase, fb);
            tma_ld_cg2(st + ST_AL, &tmAl, c * KC, rbase, fb);
            // B: this CTA holds its 128-row half of the N=256 region
            tma_ld_cg2(st + ST_B, &tmB, c * KC, cbase + rank * 128, fb);
            if (++s == NST) { s = 0; k++; }
        }
    }

    // ---------------- MMA driver (leader CTA, warp 5, lane 0) ----------------
    if (rank == 0 && wid == 5 && lane == 0) {
        int s = 0, k = 0;
        for (int c = 0; c < NCH; c++) {
            mbar_wait(sb + OFF_FULL(s), k & 1);
            const uint32_t st = sb + OFF_ST(s);
            const uint64_t ah = mk_desc64(st + ST_AH);
            const uint64_t al = mk_desc64(st + ST_AL);
            const uint64_t bd = mk_desc64(st + ST_B);
            const uint32_t en0 = (c > 0) ? 1u : 0u;
            // hi digit -> D1 (cols 0-255); lo digit -> D0 (cols 256-511)
            // k-steps: K=32 int8 = 32B = +2 desc units
            mma_i8_ss_cg2(tmem,       ah,     bd,     MMA_IDESC, en0);
            mma_i8_ss_cg2(tmem,       ah + 2, bd + 2, MMA_IDESC, 1u);
            mma_i8_ss_cg2(tmem + 256, al,     bd,     MMA_IDESC, en0);
            mma_i8_ss_cg2(tmem + 256, al + 2, bd + 2, MMA_IDESC, 1u);
            tc_commit_mc2(sb + OFF_EMPTY(s));
            if (c == NCH - 1) tc_commit_mc2(sb + OFF_DONE);
            if (++s == NST) { s = 0; k++; }
        }
    }

    // ---------------- epilogue warps (warps 0-3, BOTH CTAs) ----------------
    if (wid < 4) {
        float* s_sc = (float*)(smem + OFF_PRM);
        float* s_zp = s_sc + BN;
        float* s_bi = s_zp + BN;
        for (int i = tid; i < BN; i += 128) {
            s_sc[i] = scales[cbase + i];
            s_zp[i] = zps[cbase + i];
            s_bi[i] = biasv[cbase + i];
        }
        asm volatile("bar.sync 1, 128;" ::: "memory");

        mbar_wait(sb + OFF_DONE, 0);
        asm volatile("tcgen05.fence::after_thread_sync;" ::: "memory");

        const int row = rbase + wid * 32 + lane;   // this CTA's TMEM lanes
        const float rs  = rowsum[row];
        const float srw = rscale[row];
        float* orow = out + (size_t)row * OUT_F + cbase;
#pragma unroll 1
        for (int blk = 0; blk < 8; blk++) {
            uint32_t r1[32], r0[32];
            TC_LD_X32(r1, tmem + blk * 32);          // hi-digit s32
            TC_LD_X32(r0, tmem + 256 + blk * 32);    // lo-digit s32
            asm volatile("tcgen05.wait::ld.sync.aligned;" ::: "memory");
#pragma unroll
            for (int c = 0; c < 32; c += 4) {
                const int col = blk * 32 + c;
                float4 v;
#pragma unroll
                for (int j = 0; j < 4; j++) {
                    const float acc = fmaf(128.f, (float)(int)r1[c + j],
                                           (float)(int)r0[c + j]);
                    const float g = srw * acc;
                    (&v.x)[j] = (g - s_zp[col + j] * rs) * s_sc[col + j] + s_bi[col + j];
                }
                *reinterpret_cast<float4*>(orow + col) = v;
            }
        }
    }

    __syncthreads();
    CLUSTER_SYNC_();   // both CTAs done with TMEM before collective dealloc
    if (wid == 0) {
        asm volatile("tcgen05.dealloc.cta_group::2.sync.aligned.b32 %0, %1;"
                     :: "r"(tmem), "r"(512u));
    }
    CLUSTER_SYNC_();
#else
    (void)tmAh; (void)tmAl; (void)tmB; (void)scales; (void)zps; (void)biasv;
    (void)rowsum; (void)rscale; (void)out;
#endif
}

// ============================================================================
// Host launcher
// ============================================================================
typedef CUresult (*tme_fn_t)(CUtensorMap*, CUtensorMapDataType, cuuint32_t, void*,
                             const cuuint64_t*, const cuuint64_t*,
                             const cuuint32_t*, const cuuint32_t*,
                             CUtensorMapInterleave, CUtensorMapSwizzle,
                             CUtensorMapL2promotion, CUtensorMapFloatOOBfill);

extern "C" void kernel_launch(void* const* d_in, const int* in_sizes, int n_in,
                              void* d_out, int out_size) {
    const float* input  = (const float*)d_in[0];
    const int*   w      = (const int*)d_in[1];
    const float* scales = (const float*)d_in[2];
    const float* zps    = (const float*)d_in[3];
    const float* bias   = (const float*)d_in[4];
    float* out = (float*)d_out;
    (void)in_sizes; (void)n_in; (void)out_size;

    void *pW = nullptr, *pAh = nullptr, *pAl = nullptr, *pRs = nullptr, *pSc = nullptr;
    cudaGetSymbolAddress(&pW,  g_W8);
    cudaGetSymbolAddress(&pAh, g_Ah);
    cudaGetSymbolAddress(&pAl, g_Al);
    cudaGetSymbolAddress(&pRs, g_rowsum);
    cudaGetSymbolAddress(&pSc, g_rscale);

    tme_fn_t encode = nullptr;
    cudaDriverEntryPointQueryResult qr;
    cudaGetDriverEntryPoint("cuTensorMapEncodeTiled", (void**)&encode,
                            cudaEnableDefault, &qr);

    CUtensorMap mAh, mAl, mB;
    __builtin_memset(&mAh, 0, sizeof(mAh));
    __builtin_memset(&mAl, 0, sizeof(mAl));
    __builtin_memset(&mB, 0, sizeof(mB));
    if (encode) {
        {
            cuuint64_t dims[3]    = { IN_F, TOKENS, 1 };
            cuuint64_t strides[2] = { IN_F, (cuuint64_t)IN_F * TOKENS };
            cuuint32_t box[3]     = { KC, 128, 1 };    // 64B rows (SW64)
            cuuint32_t es[3]      = { 1, 1, 1 };
            encode(&mAh, CU_TENSOR_MAP_DATA_TYPE_UINT8, 3, pAh, dims, strides, box, es,
                   CU_TENSOR_MAP_INTERLEAVE_NONE, CU_TENSOR_MAP_SWIZZLE_64B,
                   CU_TENSOR_MAP_L2_PROMOTION_L2_128B, CU_TENSOR_MAP_FLOAT_OOB_FILL_NONE);
            encode(&mAl, CU_TENSOR_MAP_DATA_TYPE_UINT8, 3, pAl, dims, strides, box, es,
                   CU_TENSOR_MAP_INTERLEAVE_NONE, CU_TENSOR_MAP_SWIZZLE_64B,
                   CU_TENSOR_MAP_L2_PROMOTION_L2_128B, CU_TENSOR_MAP_FLOAT_OOB_FILL_NONE);
        }
        {
            cuuint64_t dims[3]    = { IN_F, OUT_F, 1 };
            cuuint64_t strides[2] = { IN_F, (cuuint64_t)IN_F * OUT_F };
            cuuint32_t box[3]     = { KC, 128, 1 };    // 128-row pieces per CTA
            cuuint32_t es[3]      = { 1, 1, 1 };
            encode(&mB, CU_TENSOR_MAP_DATA_TYPE_UINT8, 3, pW, dims, strides, box, es,
                   CU_TENSOR_MAP_INTERLEAVE_NONE, CU_TENSOR_MAP_SWIZZLE_64B,
                   CU_TENSOR_MAP_L2_PROMOTION_L2_128B, CU_TENSOR_MAP_FLOAT_OOB_FILL_NONE);
        }
    }

    cudaFuncSetAttribute(qlinear_tc, cudaFuncAttributeMaxDynamicSharedMemorySize,
                         SMEM_TOTAL);

    // preprocessing
    {
        int n4 = (OUT_F * IN_F) / 4;
        k_pack_w<<<(n4 + 255) / 256, 256>>>((const int4*)w, (char4*)pW, n4);
    }
    k_convert_x<<<TOKENS, 256>>>((const float4*)input, (char4*)pAh, (char4*)pAl,
                                 (float*)pRs, (float*)pSc);

    // GEMM: grid.x = 32 M-CTAs (cg2 pairs), grid.y = 43 N tiles (exact)
    dim3 grid(TOKENS / 128, OUT_F / BN);
    qlinear_tc<<<grid, 192, SMEM_TOTAL>>>(mAh, mAl, mB, scales, zps, bias,
                                          (const float*)pRs, (const float*)pSc, out);
}

// round 10
// speedup vs baseline: 2.0831x; 1.1040x over previous
#include <cuda_runtime.h>
#include <cuda.h>
#include <cuda_bf16.h>
#include <cstdint>
#include <cstdio>

// ============================================================================
// QuantizedLinear via two-digit int8 tcgen05 GEMM, persistent cg2 clusters.
//   out[t,o] = (sum_k x[t,k]*(w[o,k]-zp[o])) * scale[o] + bias[o]
//   M=TOKENS=4096, N=OUT_F=11008, K=IN_F=4096
//
// W int8-exact. x fixed-point per row: x ~= s_row*(128*h + l), h,l in s8.
// Two kind::i8 GEMMs (s32 in TMEM): D1 = h.W^T (cols 0-255), D0 = l.W^T
// (cols 256-511). out = (s_row*(128*D1+D0) - zp*rowsum)*scale + bias.
//
// Persistent: 74 cg2 pairs each process ~9-10 of the 688 256x256 tiles.
// Continuous 8-stage TMA ring across tile boundaries; EPI_FREE barrier lets
// the producer prefetch tile t+1 while epilogue drains tile t's TMEM.
// Warps: 0-3 epilogue, 4 producer (both CTAs), 5 MMA driver (leader).
// ============================================================================

#define TOKENS 4096
#define IN_F   4096
#define OUT_F  11008

#define BN    256               // N per pair-tile (one N=256 MMA region)
#define KC    64
#define NCH   (IN_F / KC)       // 64 chunks per tile
#define NST   8                 // pipeline stages
#define NPAIR 74
#define NTILE 688               // 16 M-pairs x 43 N-tiles

#if defined(__CUDA_ARCH__) && (defined(__CUDA_ARCH_FEAT_SM100_ALL) || defined(__CUDA_ARCH_FEAT_SM103_ALL) || defined(__CUDA_ARCH_FEAT_SM101_ALL))
#define HAVE_TCGEN05 1
#else
#define HAVE_TCGEN05 0
#endif

// ---- dynamic SMEM layout (per CTA) ----
#define OFF_TMEM     0
#define OFF_FULL(s)  (16 + 8*(s))     // 16..79
#define OFF_EMPTY(s) (96 + 8*(s))     // 96..159
#define OFF_DONE     176
#define OFF_EPIF     184
#define STAGE_STRIDE 24576            // AH 8K + AL 8K + B 8K (int8)
#define OFF_ST(s)    (1024 + (s)*STAGE_STRIDE)
#define ST_AH        0
#define ST_AL        8192
#define ST_B         16384
#define OFF_PRM      (1024 + NST*STAGE_STRIDE)   // 197632
#define SMEM_TOTAL   (OFF_PRM + 3*BN*4)          // 200704

// idesc kind::i8 cg2: c=S32(2)@[4:6), a=S8(1)@[7:10), b=S8(1)@[10:13),
// N/8 @[17:23), M_total/16 @[24:29)
#define MMA_IDESC ((2u<<4) | (1u<<7) | (1u<<10) | ((BN/8)<<17) | ((256/16)<<24))

// ---- scratch (device globals: no allocation allowed) ----
__device__ __align__(1024) int8_t g_W8[(size_t)OUT_F  * IN_F];
__device__ __align__(1024) int8_t g_Ah[(size_t)TOKENS * IN_F];
__device__ __align__(1024) int8_t g_Al[(size_t)TOKENS * IN_F];
__device__ float g_rowsum[TOKENS];
__device__ float g_rscale[TOKENS];

// ============================================================================
// Common helpers
// ============================================================================
__device__ __forceinline__ uint32_t smem_u32(const void* p) {
    uint32_t a;
    asm("{ .reg .u64 t; cvta.to.shared.u64 t, %1; cvt.u32.u64 %0, t; }"
        : "=r"(a) : "l"(p));
    return a;
}

// ============================================================================
// Fused preprocessing: blocks [0, NBLK_W) pack W; blocks [NBLK_W, +TOKENS)
// do per-row two-digit quantization of x (+ rowsum/rowscale).
// ============================================================================
#define NBLK_W ((OUT_F * IN_F / 4) / 256)   // 44032

__global__ void k_prep(const int4* __restrict__ w4, char4* __restrict__ W,
                       const float4* __restrict__ x4,
                       char4* __restrict__ hi, char4* __restrict__ lo,
                       float* __restrict__ rs, float* __restrict__ rsc) {
    __shared__ float redM[8], redS[8], bc[1];
    const int tid = threadIdx.x;
    if (blockIdx.x < NBLK_W) {
        const int i = blockIdx.x * 256 + tid;
        int4 v = w4[i];
        W[i] = make_char4((signed char)v.x, (signed char)v.y,
                          (signed char)v.z, (signed char)v.w);
        return;
    }
    const int row = blockIdx.x - NBLK_W;
    const float4* px = x4 + (size_t)row * (IN_F / 4);
    float mx = 0.f, sm = 0.f;
    for (int i = tid; i < IN_F / 4; i += 256) {
        float4 v = px[i];
        mx = fmaxf(mx, fmaxf(fmaxf(fabsf(v.x), fabsf(v.y)),
                             fmaxf(fabsf(v.z), fabsf(v.w))));
        sm += v.x + v.y + v.z + v.w;
    }
#pragma unroll
    for (int o = 16; o > 0; o >>= 1) {
        mx = fmaxf(mx, __shfl_xor_sync(0xffffffffu, mx, o));
        sm += __shfl_xor_sync(0xffffffffu, sm, o);
    }
    if ((tid & 31) == 0) { redM[tid >> 5] = mx; redS[tid >> 5] = sm; }
    __syncthreads();
    if (tid < 8) {
        float m = redM[tid], s = redS[tid];
#pragma unroll
        for (int o = 4; o > 0; o >>= 1) {
            m = fmaxf(m, __shfl_xor_sync(0xffu, m, o));
            s += __shfl_xor_sync(0xffu, s, o);
        }
        if (tid == 0) {
            bc[0]    = (m > 1e-30f) ? (16000.f / m) : 0.f;   // inv scale
            rs[row]  = s;
            rsc[row] = (m > 1e-30f) ? (m / 16000.f) : 0.f;
        }
    }
    __syncthreads();
    const float inv = bc[0];
    char4* ph = hi + (size_t)row * (IN_F / 4);
    char4* pl = lo + (size_t)row * (IN_F / 4);
    for (int i = tid; i < IN_F / 4; i += 256) {
        float4 v = px[i];
        const float* f = &v.x;
        signed char hd[4], ld[4];
#pragma unroll
        for (int j = 0; j < 4; j++) {
            int vq = __float2int_rn(f[j] * inv);   // |vq| <= 16000
            int h  = (vq + 64) >> 7;               // |h| <= 126
            int l  = vq - (h << 7);                // in [-64, 63]
            hd[j] = (signed char)h;
            ld[j] = (signed char)l;
        }
        ph[i] = make_char4(hd[0], hd[1], hd[2], hd[3]);
        pl[i] = make_char4(ld[0], ld[1], ld[2], ld[3]);
    }
}

// ============================================================================
// tcgen05 PTX helpers (guarded)
// ============================================================================
#if HAVE_TCGEN05
#define MBAR_INIT(addr, cnt) \
    asm volatile("mbarrier.init.shared.b64 [%0], %1;" :: "r"(addr), "r"((uint32_t)(cnt)) : "memory")
#define MBAR_EXPECT(addr, bytes) \
    asm volatile("mbarrier.arrive.expect_tx.shared.b64 _, [%0], %1;" :: "r"(addr), "r"((uint32_t)(bytes)) : "memory")

__device__ __forceinline__ void mbar_wait(uint32_t addr, uint32_t parity) {
    uint32_t done;
    asm volatile(
        "{\n\t.reg .pred p;\n\t"
        "mbarrier.try_wait.parity.acquire.cta.shared::cta.b64 p, [%1], %2;\n\t"
        "selp.b32 %0, 1, 0, p;\n\t}"
        : "=r"(done) : "r"(addr), "r"(parity) : "memory");
    if (!done) {
        asm volatile(
            "{\n\t.reg .pred P1;\n\t"
            "WL_%=:\n\t"
            "mbarrier.try_wait.parity.acquire.cta.shared::cta.b64 P1, [%0], %1, 0x989680;\n\t"
            "@P1 bra.uni WD_%=;\n\t"
            "bra.uni WL_%=;\n\t"
            "WD_%=:\n\t}"
            :: "r"(addr), "r"(parity) : "memory");
    }
}

// cg2 TMA 3D load: both CTAs execute; complete_tx targets leader CTA's barrier
// via Sm100MmaPeerBitMask (clear bit 24 of the local barrier address).
__device__ __forceinline__ void tma_ld_cg2(uint32_t smem, const void* map,
                                           int x, int y, uint32_t mbar) {
    asm volatile(
        "{\n\t.reg .b32 lb;\n\t"
        "and.b32 lb, %5, 0xFEFFFFFF;\n\t"
        "cp.async.bulk.tensor.3d.cta_group::2.shared::cluster.global"
        ".tile.mbarrier::complete_tx::bytes [%0], [%1, {%2, %3, %4}], [lb];\n\t}"
        :: "r"(smem), "l"(map), "r"(x), "r"(y), "r"(0), "r"(mbar) : "memory");
}

// K-major SW64 smem descriptor: layout=4 (SW64), version=1, SBO=32, LBO=1
__device__ __forceinline__ uint64_t mk_desc64(uint32_t addr) {
    const uint64_t BASE = (4ull << 61) | (1ull << 46) | (32ull << 32) | (1ull << 16);
    return BASE | ((uint64_t)(addr >> 4) & 0x3FFF);
}

__device__ __forceinline__ void mma_i8_ss_cg2(uint32_t d, uint64_t a, uint64_t b,
                                              uint32_t idesc, uint32_t en) {
    asm volatile(
        "{\n\t.reg .pred p;\n\t"
        "setp.ne.u32 p, %4, 0;\n\t"
        "tcgen05.mma.cta_group::2.kind::i8 [%0], %1, %2, %3, "
        "{%5, %5, %5, %5, %5, %5, %5, %5}, p;\n\t}"
        :: "r"(d), "l"(a), "l"(b), "r"(idesc), "r"(en), "r"(0u) : "memory");
}

__device__ __forceinline__ void tc_commit_mc2(uint32_t mbar) {
    asm volatile(
        "tcgen05.commit.cta_group::2.mbarrier::arrive::one.shared::cluster"
        ".multicast::cluster.b64 [%0], %1;"
        :: "r"(mbar), "h"((uint16_t)0x3) : "memory");
}

// arrive on cluster-rank-0's mbarrier at the same smem offset
__device__ __forceinline__ void mbar_arrive_rank0(uint32_t addr) {
    asm volatile(
        "{\n\t.reg .b32 ra;\n\t"
        "mapa.shared::cluster.u32 ra, %0, %1;\n\t"
        "mbarrier.arrive.shared::cluster.b64 _, [ra];\n\t}"
        :: "r"(addr), "r"(0) : "memory");
}

#define TC_LD_X32(r, tmem_addr) \
    asm volatile( \
        "tcgen05.ld.sync.aligned.32x32b.x32.b32 " \
        "{%0, %1, %2, %3, %4, %5, %6, %7, " \
        " %8, %9, %10, %11, %12, %13, %14, %15, " \
        " %16, %17, %18, %19, %20, %21, %22, %23, " \
        " %24, %25, %26, %27, %28, %29, %30, %31}, [%32];" \
        : "=r"((r)[0]),  "=r"((r)[1]),  "=r"((r)[2]),  "=r"((r)[3]), \
          "=r"((r)[4]),  "=r"((r)[5]),  "=r"((r)[6]),  "=r"((r)[7]), \
          "=r"((r)[8]),  "=r"((r)[9]),  "=r"((r)[10]), "=r"((r)[11]), \
          "=r"((r)[12]), "=r"((r)[13]), "=r"((r)[14]), "=r"((r)[15]), \
          "=r"((r)[16]), "=r"((r)[17]), "=r"((r)[18]), "=r"((r)[19]), \
          "=r"((r)[20]), "=r"((r)[21]), "=r"((r)[22]), "=r"((r)[23]), \
          "=r"((r)[24]), "=r"((r)[25]), "=r"((r)[26]), "=r"((r)[27]), \
          "=r"((r)[28]), "=r"((r)[29]), "=r"((r)[30]), "=r"((r)[31]) \
        : "r"(tmem_addr))

#define CLUSTER_SYNC_() do { \
    asm volatile("barrier.cluster.arrive.aligned;" ::: "memory"); \
    asm volatile("barrier.cluster.wait.aligned;" ::: "memory"); \
} while (0)
#endif  // HAVE_TCGEN05

// ============================================================================
// Persistent GEMM kernel: 74 cg2 pairs, each owns tiles t = pair + ti*74.
//   tile t: M-pair mp = t & 15 (rows mp*256 + rank*128), N-tile nt = t >> 4.
// ============================================================================
__global__ void __launch_bounds__(192, 1) __cluster_dims__(2, 1, 1) qlinear_tc(
    const __grid_constant__ CUtensorMap tmAh,
    const __grid_constant__ CUtensorMap tmAl,
    const __grid_constant__ CUtensorMap tmB,
    const float* __restrict__ scales,
    const float* __restrict__ zps,
    const float* __restrict__ biasv,
    const float* __restrict__ rowsum,
    const float* __restrict__ rscale,
    float* __restrict__ out)
{
#if HAVE_TCGEN05
    extern __shared__ __align__(1024) char smem[];
    const uint32_t sb = smem_u32(smem);
    const int tid  = threadIdx.x;
    const int wid  = tid >> 5;
    const int lane = tid & 31;
    const int rank = blockIdx.x & 1;           // cg2 pair rank
    const int pair = blockIdx.x >> 1;          // 0..73
    const int ntiles = (NTILE - pair + NPAIR - 1) / NPAIR;

    if (wid == 0) {
        asm volatile("tcgen05.alloc.cta_group::2.sync.aligned.shared::cta.b32 [%0], %1;"
                     :: "r"(sb + OFF_TMEM), "r"(512u) : "memory");
        asm volatile("tcgen05.relinquish_alloc_permit.cta_group::2.sync.aligned;");
    }
    if (tid == 0) {
        for (int s = 0; s < NST; s++) {
            MBAR_INIT(sb + OFF_FULL(s), 1);
            MBAR_INIT(sb + OFF_EMPTY(s), 1);
        }
        MBAR_INIT(sb + OFF_DONE, 1);
        MBAR_INIT(sb + OFF_EPIF, 2);   // one arrive per CTA's epilogue
        asm volatile("fence.proxy.async.shared::cta;" ::: "memory");
    }
    __syncthreads();
    CLUSTER_SYNC_();   // peer barriers must be live before cg2 TMA / commits

    uint32_t tmem;
    asm volatile("ld.shared.b32 %0, [%1];" : "=r"(tmem) : "r"(sb + OFF_TMEM));

    // ---------------- producer warp (warp 4, lane 0, BOTH CTAs) ----------------
    if (wid == 4 && lane == 0) {
        int s = 0, k = 0;
        for (int ti = 0; ti < ntiles; ti++) {
            const int t  = pair + ti * NPAIR;
            const int rb = (t & 15) * 256 + rank * 128;
            const int cb = (t >> 4) * 256 + rank * 128;   // B rows for this CTA
            for (int c = 0; c < NCH; c++) {
                if (k > 0) mbar_wait(sb + OFF_EMPTY(s), (k - 1) & 1);
                if (rank == 0) MBAR_EXPECT(sb + OFF_FULL(s), 2u * STAGE_STRIDE);
                const uint32_t st = sb + OFF_ST(s);
                const uint32_t fb = sb + OFF_FULL(s);
                tma_ld_cg2(st + ST_AH, &tmAh, c * KC, rb, fb);
                tma_ld_cg2(st + ST_AL, &tmAl, c * KC, rb, fb);
                tma_ld_cg2(st + ST_B,  &tmB,  c * KC, cb, fb);
                if (++s == NST) { s = 0; k++; }
            }
        }
    }

    // ---------------- MMA driver (leader CTA, warp 5, lane 0) ----------------
    if (rank == 0 && wid == 5 && lane == 0) {
        int s = 0, k = 0;
        for (int ti = 0; ti < ntiles; ti++) {
            if (ti > 0) {   // both CTAs' epilogues must have drained tile ti-1
                mbar_wait(sb + OFF_EPIF, (ti - 1) & 1);
                asm volatile("tcgen05.fence::after_thread_sync;" ::: "memory");
            }
            for (int c = 0; c < NCH; c++) {
                mbar_wait(sb + OFF_FULL(s), k & 1);
                const uint32_t st = sb + OFF_ST(s);
                const uint64_t ah = mk_desc64(st + ST_AH);
                const uint64_t al = mk_desc64(st + ST_AL);
                const uint64_t bd = mk_desc64(st + ST_B);
                const uint32_t en0 = (c > 0) ? 1u : 0u;
                // K=32 int8 per dispatch = 32B = +2 desc units
                mma_i8_ss_cg2(tmem,       ah,     bd,     MMA_IDESC, en0);
                mma_i8_ss_cg2(tmem,       ah + 2, bd + 2, MMA_IDESC, 1u);
                mma_i8_ss_cg2(tmem + 256, al,     bd,     MMA_IDESC, en0);
                mma_i8_ss_cg2(tmem + 256, al + 2, bd + 2, MMA_IDESC, 1u);
                tc_commit_mc2(sb + OFF_EMPTY(s));
                if (c == NCH - 1) tc_commit_mc2(sb + OFF_DONE);
                if (++s == NST) { s = 0; k++; }
            }
        }
    }

    // ---------------- epilogue warps (warps 0-3, BOTH CTAs) ----------------
    if (wid < 4) {
        float* s_sc = (float*)(smem + OFF_PRM);
        float* s_zp = s_sc + BN;
        float* s_bi = s_zp + BN;
        for (int ti = 0; ti < ntiles; ti++) {
            const int t  = pair + ti * NPAIR;
            const int cb = (t >> 4) * 256;
            const int row = (t & 15) * 256 + rank * 128 + wid * 32 + lane;
            for (int i = tid; i < BN; i += 128) {
                s_sc[i] = scales[cb + i];
                s_zp[i] = zps[cb + i];
                s_bi[i] = biasv[cb + i];
            }
            asm volatile("bar.sync 1, 128;" ::: "memory");

            mbar_wait(sb + OFF_DONE, ti & 1);
            asm volatile("tcgen05.fence::after_thread_sync;" ::: "memory");

            const float rs  = rowsum[row];
            const float srw = rscale[row];
            float* orow = out + (size_t)row * OUT_F + cb;
#pragma unroll 1
            for (int blk = 0; blk < 8; blk++) {
                uint32_t r1[32], r0[32];
                TC_LD_X32(r1, tmem + blk * 32);          // hi-digit s32
                TC_LD_X32(r0, tmem + 256 + blk * 32);    // lo-digit s32
                asm volatile("tcgen05.wait::ld.sync.aligned;" ::: "memory");
#pragma unroll
                for (int c = 0; c < 32; c += 4) {
                    const int col = blk * 32 + c;
                    float4 v;
#pragma unroll
                    for (int j = 0; j < 4; j++) {
                        const float acc = fmaf(128.f, (float)(int)r1[c + j],
                                               (float)(int)r0[c + j]);
                        (&v.x)[j] = (srw * acc - s_zp[col + j] * rs) * s_sc[col + j]
                                    + s_bi[col + j];
                    }
                    *reinterpret_cast<float4*>(orow + col) = v;
                }
            }
            asm volatile("tcgen05.fence::before_thread_sync;" ::: "memory");
            asm volatile("bar.sync 1, 128;" ::: "memory");   // all 4 warps done reading
            if (tid == 0) mbar_arrive_rank0(sb + OFF_EPIF);  // release next tile's MMA
        }
    }

    __syncthreads();
    CLUSTER_SYNC_();   // both CTAs done with TMEM before collective dealloc
    if (wid == 0) {
        asm volatile("tcgen05.dealloc.cta_group::2.sync.aligned.b32 %0, %1;"
                     :: "r"(tmem), "r"(512u));
    }
    CLUSTER_SYNC_();
#else
    (void)tmAh; (void)tmAl; (void)tmB; (void)scales; (void)zps; (void)biasv;
    (void)rowsum; (void)rscale; (void)out;
#endif
}

// ============================================================================
// Host launcher
// ============================================================================
typedef CUresult (*tme_fn_t)(CUtensorMap*, CUtensorMapDataType, cuuint32_t, void*,
                             const cuuint64_t*, const cuuint64_t*,
                             const cuuint32_t*, const cuuint32_t*,
                             CUtensorMapInterleave, CUtensorMapSwizzle,
                             CUtensorMapL2promotion, CUtensorMapFloatOOBfill);

extern "C" void kernel_launch(void* const* d_in, const int* in_sizes, int n_in,
                              void* d_out, int out_size) {
    const float* input  = (const float*)d_in[0];
    const int*   w      = (const int*)d_in[1];
    const float* scales = (const float*)d_in[2];
    const float* zps    = (const float*)d_in[3];
    const float* bias   = (const float*)d_in[4];
    float* out = (float*)d_out;
    (void)in_sizes; (void)n_in; (void)out_size;

    void *pW = nullptr, *pAh = nullptr, *pAl = nullptr, *pRs = nullptr, *pSc = nullptr;
    cudaGetSymbolAddress(&pW,  g_W8);
    cudaGetSymbolAddress(&pAh, g_Ah);
    cudaGetSymbolAddress(&pAl, g_Al);
    cudaGetSymbolAddress(&pRs, g_rowsum);
    cudaGetSymbolAddress(&pSc, g_rscale);

    tme_fn_t encode = nullptr;
    cudaDriverEntryPointQueryResult qr;
    cudaGetDriverEntryPoint("cuTensorMapEncodeTiled", (void**)&encode,
                            cudaEnableDefault, &qr);

    CUtensorMap mAh, mAl, mB;
    __builtin_memset(&mAh, 0, sizeof(mAh));
    __builtin_memset(&mAl, 0, sizeof(mAl));
    __builtin_memset(&mB, 0, sizeof(mB));
    if (encode) {
        {
            cuuint64_t dims[3]    = { IN_F, TOKENS, 1 };
            cuuint64_t strides[2] = { IN_F, (cuuint64_t)IN_F * TOKENS };
            cuuint32_t box[3]     = { KC, 128, 1 };    // 64B rows (SW64)
            cuuint32_t es[3]      = { 1, 1, 1 };
            encode(&mAh, CU_TENSOR_MAP_DATA_TYPE_UINT8, 3, pAh, dims, strides, box, es,
                   CU_TENSOR_MAP_INTERLEAVE_NONE, CU_TENSOR_MAP_SWIZZLE_64B,
                   CU_TENSOR_MAP_L2_PROMOTION_L2_128B, CU_TENSOR_MAP_FLOAT_OOB_FILL_NONE);
            encode(&mAl, CU_TENSOR_MAP_DATA_TYPE_UINT8, 3, pAl, dims, strides, box, es,
                   CU_TENSOR_MAP_INTERLEAVE_NONE, CU_TENSOR_MAP_SWIZZLE_64B,
                   CU_TENSOR_MAP_L2_PROMOTION_L2_128B, CU_TENSOR_MAP_FLOAT_OOB_FILL_NONE);
        }
        {
            cuuint64_t dims[3]    = { IN_F, OUT_F, 1 };
            cuuint64_t strides[2] = { IN_F, (cuuint64_t)IN_F * OUT_F };
            cuuint32_t box[3]     = { KC, 128, 1 };    // 128-row pieces per CTA
            cuuint32_t es[3]      = { 1, 1, 1 };
            encode(&mB, CU_TENSOR_MAP_DATA_TYPE_UINT8, 3, pW, dims, strides, box, es,
                   CU_TENSOR_MAP_INTERLEAVE_NONE, CU_TENSOR_MAP_SWIZZLE_64B,
                   CU_TENSOR_MAP_L2_PROMOTION_L2_128B, CU_TENSOR_MAP_FLOAT_OOB_FILL_NONE);
        }
    }

    cudaFuncSetAttribute(qlinear_tc, cudaFuncAttributeMaxDynamicSharedMemorySize,
                         SMEM_TOTAL);

    // fused preprocessing: W pack + x two-digit quantization (overlapped)
    k_prep<<<NBLK_W + TOKENS, 256>>>((const int4*)w, (char4*)pW,
                                     (const float4*)input, (char4*)pAh, (char4*)pAl,
                                     (float*)pRs, (float*)pSc);

    // persistent GEMM: 148 CTAs = 74 cg2 pairs
    qlinear_tc<<<dim3(2 * NPAIR, 1), 192, SMEM_TOTAL>>>(
        mAh, mAl, mB, scales, zps, bias,
        (const float*)pRs, (const float*)pSc, out);
}

// round 11
// speedup vs baseline: 2.1470x; 1.0307x over previous
#include <cuda_runtime.h>
#include <cuda.h>
#include <cuda_bf16.h>
#include <cstdint>
#include <cstdio>

// ============================================================================
// QuantizedLinear via two-digit int8 tcgen05 GEMM, persistent cg2 clusters.
//   out[t,o] = (sum_k x[t,k]*(w[o,k]-zp[o])) * scale[o] + bias[o]
//   M=TOKENS=4096, N=OUT_F=11008, K=IN_F=4096
//
// W int8-exact. x fixed-point per row: x ~= s_row*(128*h + l), h,l in s8.
// Two kind::i8 GEMMs (s32 in TMEM): D1 = h.W^T (cols 0-255), D0 = l.W^T
// (cols 256-511). out = (s_row*(128*D1+D0) - zp*rowsum)*scale + bias.
//
// Persistent: 74 cg2 pairs, ~9-10 of 688 tiles each, continuous 9-stage TMA
// ring across tiles. Epilogue drains TMEM with a double-buffered LDTM
// pipeline and releases EPI_FREE right after the reads complete, so next
// tile's MMA overlaps this tile's FMA/STG tail.
// Warps: 0-3 epilogue, 4 producer (both CTAs), 5 MMA driver (leader).
// ============================================================================

#define TOKENS 4096
#define IN_F   4096
#define OUT_F  11008

#define BN    256               // N per pair-tile (one N=256 MMA region)
#define KC    64
#define NCH   (IN_F / KC)       // 64 chunks per tile
#define NST   9                 // pipeline stages
#define NPAIR 74
#define NTILE 688               // 16 M-pairs x 43 N-tiles

#if defined(__CUDA_ARCH__) && (defined(__CUDA_ARCH_FEAT_SM100_ALL) || defined(__CUDA_ARCH_FEAT_SM103_ALL) || defined(__CUDA_ARCH_FEAT_SM101_ALL))
#define HAVE_TCGEN05 1
#else
#define HAVE_TCGEN05 0
#endif

// ---- dynamic SMEM layout (per CTA) ----
#define OFF_TMEM     0
#define OFF_FULL(s)  (16 + 8*(s))     // 9 stages: 16..88
#define OFF_EMPTY(s) (96 + 8*(s))     // 96..168
#define OFF_DONE     176
#define OFF_EPIF     184
#define STAGE_STRIDE 24576            // AH 8K + AL 8K + B 8K (int8)
#define OFF_ST(s)    (1024 + (s)*STAGE_STRIDE)
#define ST_AH        0
#define ST_AL        8192
#define ST_B         16384
#define OFF_PRM      (1024 + NST*STAGE_STRIDE)   // 222208
#define SMEM_TOTAL   (OFF_PRM + 3*BN*4)          // 225280

// idesc kind::i8 cg2: c=S32(2)@[4:6), a=S8(1)@[7:10), b=S8(1)@[10:13),
// N/8 @[17:23), M_total/16 @[24:29)
#define MMA_IDESC ((2u<<4) | (1u<<7) | (1u<<10) | ((BN/8)<<17) | ((256/16)<<24))

// ---- scratch (device globals: no allocation allowed) ----
__device__ __align__(1024) int8_t g_W8[(size_t)OUT_F  * IN_F];
__device__ __align__(1024) int8_t g_Ah[(size_t)TOKENS * IN_F];
__device__ __align__(1024) int8_t g_Al[(size_t)TOKENS * IN_F];
__device__ float g_rowsum[TOKENS];
__device__ float g_rscale[TOKENS];

// ============================================================================
// Common helpers
// ============================================================================
__device__ __forceinline__ uint32_t smem_u32(const void* p) {
    uint32_t a;
    asm("{ .reg .u64 t; cvta.to.shared.u64 t, %1; cvt.u32.u64 %0, t; }"
        : "=r"(a) : "l"(p));
    return a;
}

// ============================================================================
// Fused preprocessing: blocks [0, NBLK_W) pack W; blocks [NBLK_W, +TOKENS)
// do per-row two-digit quantization of x (+ rowsum/rowscale).
// ============================================================================
#define NBLK_W ((OUT_F * IN_F / 4) / 256)   // 44032

__global__ void k_prep(const int4* __restrict__ w4, char4* __restrict__ W,
                       const float4* __restrict__ x4,
                       char4* __restrict__ hi, char4* __restrict__ lo,
                       float* __restrict__ rs, float* __restrict__ rsc) {
    __shared__ float redM[8], redS[8], bc[1];
    const int tid = threadIdx.x;
    if (blockIdx.x < NBLK_W) {
        const int i = blockIdx.x * 256 + tid;
        int4 v = w4[i];
        W[i] = make_char4((signed char)v.x, (signed char)v.y,
                          (signed char)v.z, (signed char)v.w);
        return;
    }
    const int row = blockIdx.x - NBLK_W;
    const float4* px = x4 + (size_t)row * (IN_F / 4);
    float mx = 0.f, sm = 0.f;
    for (int i = tid; i < IN_F / 4; i += 256) {
        float4 v = px[i];
        mx = fmaxf(mx, fmaxf(fmaxf(fabsf(v.x), fabsf(v.y)),
                             fmaxf(fabsf(v.z), fabsf(v.w))));
        sm += v.x + v.y + v.z + v.w;
    }
#pragma unroll
    for (int o = 16; o > 0; o >>= 1) {
        mx = fmaxf(mx, __shfl_xor_sync(0xffffffffu, mx, o));
        sm += __shfl_xor_sync(0xffffffffu, sm, o);
    }
    if ((tid & 31) == 0) { redM[tid >> 5] = mx; redS[tid >> 5] = sm; }
    __syncthreads();
    if (tid < 8) {
        float m = redM[tid], s = redS[tid];
#pragma unroll
        for (int o = 4; o > 0; o >>= 1) {
            m = fmaxf(m, __shfl_xor_sync(0xffu, m, o));
            s += __shfl_xor_sync(0xffu, s, o);
        }
        if (tid == 0) {
            bc[0]    = (m > 1e-30f) ? (16000.f / m) : 0.f;   // inv scale
            rs[row]  = s;
            rsc[row] = (m > 1e-30f) ? (m / 16000.f) : 0.f;
        }
    }
    __syncthreads();
    const float inv = bc[0];
    char4* ph = hi + (size_t)row * (IN_F / 4);
    char4* pl = lo + (size_t)row * (IN_F / 4);
    for (int i = tid; i < IN_F / 4; i += 256) {
        float4 v = px[i];
        const float* f = &v.x;
        signed char hd[4], ld[4];
#pragma unroll
        for (int j = 0; j < 4; j++) {
            int vq = __float2int_rn(f[j] * inv);   // |vq| <= 16000
            int h  = (vq + 64) >> 7;               // |h| <= 126
            int l  = vq - (h << 7);                // in [-64, 63]
            hd[j] = (signed char)h;
            ld[j] = (signed char)l;
        }
        ph[i] = make_char4(hd[0], hd[1], hd[2], hd[3]);
        pl[i] = make_char4(ld[0], ld[1], ld[2], ld[3]);
    }
}

// ============================================================================
// tcgen05 PTX helpers (guarded)
// ============================================================================
#if HAVE_TCGEN05
#define MBAR_INIT(addr, cnt) \
    asm volatile("mbarrier.init.shared.b64 [%0], %1;" :: "r"(addr), "r"((uint32_t)(cnt)) : "memory")
#define MBAR_EXPECT(addr, bytes) \
    asm volatile("mbarrier.arrive.expect_tx.shared.b64 _, [%0], %1;" :: "r"(addr), "r"((uint32_t)(bytes)) : "memory")

__device__ __forceinline__ void mbar_wait(uint32_t addr, uint32_t parity) {
    uint32_t done;
    asm volatile(
        "{\n\t.reg .pred p;\n\t"
        "mbarrier.try_wait.parity.acquire.cta.shared::cta.b64 p, [%1], %2;\n\t"
        "selp.b32 %0, 1, 0, p;\n\t}"
        : "=r"(done) : "r"(addr), "r"(parity) : "memory");
    if (!done) {
        asm volatile(
            "{\n\t.reg .pred P1;\n\t"
            "WL_%=:\n\t"
            "mbarrier.try_wait.parity.acquire.cta.shared::cta.b64 P1, [%0], %1, 0x989680;\n\t"
            "@P1 bra.uni WD_%=;\n\t"
            "bra.uni WL_%=;\n\t"
            "WD_%=:\n\t}"
            :: "r"(addr), "r"(parity) : "memory");
    }
}

// relaxed wait: ONLY for waits whose post-wait SMEM accesses are async-proxy
// (TMA issue / tcgen05 MMA issue) — producer EMPTY and driver FULL waits.
__device__ __forceinline__ void mbar_wait_relaxed(uint32_t addr, uint32_t parity) {
    uint32_t done;
    asm volatile(
        "{\n\t.reg .pred p;\n\t"
        "mbarrier.try_wait.parity.relaxed.cta.shared::cta.b64 p, [%1], %2;\n\t"
        "selp.b32 %0, 1, 0, p;\n\t}"
        : "=r"(done) : "r"(addr), "r"(parity) : "memory");
    if (!done) {
        asm volatile(
            "{\n\t.reg .pred P1;\n\t"
            "RL_%=:\n\t"
            "mbarrier.try_wait.parity.relaxed.cta.shared::cta.b64 P1, [%0], %1, 0x989680;\n\t"
            "@P1 bra.uni RD_%=;\n\t"
            "bra.uni RL_%=;\n\t"
            "RD_%=:\n\t}"
            :: "r"(addr), "r"(parity) : "memory");
    }
}

// cg2 TMA 3D load: both CTAs execute; complete_tx targets leader CTA's barrier
// via Sm100MmaPeerBitMask (clear bit 24 of the local barrier address).
__device__ __forceinline__ void tma_ld_cg2(uint32_t smem, const void* map,
                                           int x, int y, uint32_t mbar) {
    asm volatile(
        "{\n\t.reg .b32 lb;\n\t"
        "and.b32 lb, %5, 0xFEFFFFFF;\n\t"
        "cp.async.bulk.tensor.3d.cta_group::2.shared::cluster.global"
        ".tile.mbarrier::complete_tx::bytes [%0], [%1, {%2, %3, %4}], [lb];\n\t}"
        :: "r"(smem), "l"(map), "r"(x), "r"(y), "r"(0), "r"(mbar) : "memory");
}

// K-major SW64 smem descriptor: layout=4 (SW64), version=1, SBO=32, LBO=1
__device__ __forceinline__ uint64_t mk_desc64(uint32_t addr) {
    const uint64_t BASE = (4ull << 61) | (1ull << 46) | (32ull << 32) | (1ull << 16);
    return BASE | ((uint64_t)(addr >> 4) & 0x3FFF);
}

__device__ __forceinline__ void mma_i8_ss_cg2(uint32_t d, uint64_t a, uint64_t b,
                                              uint32_t idesc, uint32_t en) {
    asm volatile(
        "{\n\t.reg .pred p;\n\t"
        "setp.ne.u32 p, %4, 0;\n\t"
        "tcgen05.mma.cta_group::2.kind::i8 [%0], %1, %2, %3, "
        "{%5, %5, %5, %5, %5, %5, %5, %5}, p;\n\t}"
        :: "r"(d), "l"(a), "l"(b), "r"(idesc), "r"(en), "r"(0u) : "memory");
}

__device__ __forceinline__ void tc_commit_mc2(uint32_t mbar) {
    asm volatile(
        "tcgen05.commit.cta_group::2.mbarrier::arrive::one.shared::cluster"
        ".multicast::cluster.b64 [%0], %1;"
        :: "r"(mbar), "h"((uint16_t)0x3) : "memory");
}

// arrive on cluster-rank-0's mbarrier at the same smem offset
__device__ __forceinline__ void mbar_arrive_rank0(uint32_t addr) {
    asm volatile(
        "{\n\t.reg .b32 ra;\n\t"
        "mapa.shared::cluster.u32 ra, %0, %1;\n\t"
        "mbarrier.arrive.shared::cluster.b64 _, [ra];\n\t}"
        :: "r"(addr), "r"(0) : "memory");
}

#define TC_LD_X32(r, tmem_addr) \
    asm volatile( \
        "tcgen05.ld.sync.aligned.32x32b.x32.b32 " \
        "{%0, %1, %2, %3, %4, %5, %6, %7, " \
        " %8, %9, %10, %11, %12, %13, %14, %15, " \
        " %16, %17, %18, %19, %20, %21, %22, %23, " \
        " %24, %25, %26, %27, %28, %29, %30, %31}, [%32];" \
        : "=r"((r)[0]),  "=r"((r)[1]),  "=r"((r)[2]),  "=r"((r)[3]), \
          "=r"((r)[4]),  "=r"((r)[5]),  "=r"((r)[6]),  "=r"((r)[7]), \
          "=r"((r)[8]),  "=r"((r)[9]),  "=r"((r)[10]), "=r"((r)[11]), \
          "=r"((r)[12]), "=r"((r)[13]), "=r"((r)[14]), "=r"((r)[15]), \
          "=r"((r)[16]), "=r"((r)[17]), "=r"((r)[18]), "=r"((r)[19]), \
          "=r"((r)[20]), "=r"((r)[21]), "=r"((r)[22]), "=r"((r)[23]), \
          "=r"((r)[24]), "=r"((r)[25]), "=r"((r)[26]), "=r"((r)[27]), \
          "=r"((r)[28]), "=r"((r)[29]), "=r"((r)[30]), "=r"((r)[31]) \
        : "r"(tmem_addr))

#define CLUSTER_SYNC_() do { \
    asm volatile("barrier.cluster.arrive.aligned;" ::: "memory"); \
    asm volatile("barrier.cluster.wait.aligned;" ::: "memory"); \
} while (0)
#endif  // HAVE_TCGEN05

// ============================================================================
// Persistent GEMM kernel: 74 cg2 pairs, each owns tiles t = pair + ti*74.
//   tile t: M-pair mp = t & 15 (rows mp*256 + rank*128), N-tile nt = t >> 4.
// ============================================================================
__global__ void __launch_bounds__(192, 1) __cluster_dims__(2, 1, 1) qlinear_tc(
    const __grid_constant__ CUtensorMap tmAh,
    const __grid_constant__ CUtensorMap tmAl,
    const __grid_constant__ CUtensorMap tmB,
    const float* __restrict__ scales,
    const float* __restrict__ zps,
    const float* __restrict__ biasv,
    const float* __restrict__ rowsum,
    const float* __restrict__ rscale,
    float* __restrict__ out)
{
#if HAVE_TCGEN05
    extern __shared__ __align__(1024) char smem[];
    const uint32_t sb = smem_u32(smem);
    const int tid  = threadIdx.x;
    const int wid  = tid >> 5;
    const int lane = tid & 31;
    const int rank = blockIdx.x & 1;           // cg2 pair rank
    const int pair = blockIdx.x >> 1;          // 0..73
    const int ntiles = (NTILE - pair + NPAIR - 1) / NPAIR;

    if (wid == 0) {
        asm volatile("tcgen05.alloc.cta_group::2.sync.aligned.shared::cta.b32 [%0], %1;"
                     :: "r"(sb + OFF_TMEM), "r"(512u) : "memory");
        asm volatile("tcgen05.relinquish_alloc_permit.cta_group::2.sync.aligned;");
    }
    if (tid == 0) {
        for (int s = 0; s < NST; s++) {
            MBAR_INIT(sb + OFF_FULL(s), 1);
            MBAR_INIT(sb + OFF_EMPTY(s), 1);
        }
        MBAR_INIT(sb + OFF_DONE, 1);
        MBAR_INIT(sb + OFF_EPIF, 2);   // one arrive per CTA's epilogue
        asm volatile("fence.proxy.async.shared::cta;" ::: "memory");
    }
    __syncthreads();
    CLUSTER_SYNC_();   // peer barriers must be live before cg2 TMA / commits

    uint32_t tmem;
    asm volatile("ld.shared.b32 %0, [%1];" : "=r"(tmem) : "r"(sb + OFF_TMEM));

    // ---------------- producer warp (warp 4, lane 0, BOTH CTAs) ----------------
    if (wid == 4 && lane == 0) {
        int s = 0, k = 0;
        for (int ti = 0; ti < ntiles; ti++) {
            const int t  = pair + ti * NPAIR;
            const int rb = (t & 15) * 256 + rank * 128;
            const int cb = (t >> 4) * 256 + rank * 128;   // B rows for this CTA
            for (int c = 0; c < NCH; c++) {
                if (k > 0) mbar_wait_relaxed(sb + OFF_EMPTY(s), (k - 1) & 1);
                if (rank == 0) MBAR_EXPECT(sb + OFF_FULL(s), 2u * STAGE_STRIDE);
                const uint32_t st = sb + OFF_ST(s);
                const uint32_t fb = sb + OFF_FULL(s);
                tma_ld_cg2(st + ST_AH, &tmAh, c * KC, rb, fb);
                tma_ld_cg2(st + ST_AL, &tmAl, c * KC, rb, fb);
                tma_ld_cg2(st + ST_B,  &tmB,  c * KC, cb, fb);
                if (++s == NST) { s = 0; k++; }
            }
        }
    }

    // ---------------- MMA driver (leader CTA, warp 5, lane 0) ----------------
    if (rank == 0 && wid == 5 && lane == 0) {
        int s = 0, k = 0;
        for (int ti = 0; ti < ntiles; ti++) {
            if (ti > 0) {   // both CTAs' epilogues must have DRAINED tile ti-1
                mbar_wait(sb + OFF_EPIF, (ti - 1) & 1);
                asm volatile("tcgen05.fence::after_thread_sync;" ::: "memory");
            }
            for (int c = 0; c < NCH; c++) {
                mbar_wait_relaxed(sb + OFF_FULL(s), k & 1);
                const uint32_t st = sb + OFF_ST(s);
                const uint64_t ah = mk_desc64(st + ST_AH);
                const uint64_t al = mk_desc64(st + ST_AL);
                const uint64_t bd = mk_desc64(st + ST_B);
                const uint32_t en0 = (c > 0) ? 1u : 0u;
                // K=32 int8 per dispatch = 32B = +2 desc units
                mma_i8_ss_cg2(tmem,       ah,     bd,     MMA_IDESC, en0);
                mma_i8_ss_cg2(tmem,       ah + 2, bd + 2, MMA_IDESC, 1u);
                mma_i8_ss_cg2(tmem + 256, al,     bd,     MMA_IDESC, en0);
                mma_i8_ss_cg2(tmem + 256, al + 2, bd + 2, MMA_IDESC, 1u);
                tc_commit_mc2(sb + OFF_EMPTY(s));
                if (c == NCH - 1) tc_commit_mc2(sb + OFF_DONE);
                if (++s == NST) { s = 0; k++; }
            }
        }
    }

    // ---------------- epilogue warps (warps 0-3, BOTH CTAs) ----------------
    if (wid < 4) {
        float* s_sc = (float*)(smem + OFF_PRM);
        float* s_zp = s_sc + BN;
        float* s_bi = s_zp + BN;
        for (int ti = 0; ti < ntiles; ti++) {
            const int t  = pair + ti * NPAIR;
            const int cb = (t >> 4) * 256;
            const int row = (t & 15) * 256 + rank * 128 + wid * 32 + lane;
            for (int i = tid; i < BN; i += 128) {
                s_sc[i] = scales[cb + i];
                s_zp[i] = zps[cb + i];
                s_bi[i] = biasv[cb + i];
            }
            asm volatile("bar.sync 1, 128;" ::: "memory");

            mbar_wait(sb + OFF_DONE, ti & 1);
            asm volatile("tcgen05.fence::after_thread_sync;" ::: "memory");

            const float rs  = rowsum[row];
            const float srw = rscale[row];
            float* orow = out + (size_t)row * OUT_F + cb;

            // double-buffered TMEM drain: loads for blk+1 fly while blk is
            // processed; EPIF released right after the LAST read completes.
            uint32_t r1a[32], r0a[32], r1b[32], r0b[32];
            TC_LD_X32(r1a, tmem);
            TC_LD_X32(r0a, tmem + 256);
#pragma unroll
            for (int blk = 0; blk < 8; blk++) {
                asm volatile("tcgen05.wait::ld.sync.aligned;" ::: "memory");
                if (blk < 7) {
                    uint32_t* R1n = (blk & 1) ? r1a : r1b;
                    uint32_t* R0n = (blk & 1) ? r0a : r0b;
                    TC_LD_X32(R1n, tmem + (blk + 1) * 32);
                    TC_LD_X32(R0n, tmem + 256 + (blk + 1) * 32);
                } else {
                    // all 16 reads retired in this warp; sync the 4 epilogue
                    // warps of this CTA, then release TMEM for next tile's MMA
                    asm volatile("tcgen05.fence::before_thread_sync;" ::: "memory");
                    asm volatile("bar.sync 2, 128;" ::: "memory");
                    if (tid == 0) mbar_arrive_rank0(sb + OFF_EPIF);
                }
                const uint32_t* R1 = (blk & 1) ? r1b : r1a;
                const uint32_t* R0 = (blk & 1) ? r0b : r0a;
#pragma unroll
                for (int c = 0; c < 32; c += 4) {
                    const int col = blk * 32 + c;
                    float4 v;
#pragma unroll
                    for (int j = 0; j < 4; j++) {
                        const float acc = fmaf(128.f, (float)(int)R1[c + j],
                                               (float)(int)R0[c + j]);
                        (&v.x)[j] = (srw * acc - s_zp[col + j] * rs) * s_sc[col + j]
                                    + s_bi[col + j];
                    }
                    *reinterpret_cast<float4*>(orow + col) = v;
                }
            }
            // protect s_sc/s_zp/s_bi against next tile's reload
            asm volatile("bar.sync 1, 128;" ::: "memory");
        }
    }

    __syncthreads();
    CLUSTER_SYNC_();   // both CTAs done with TMEM before collective dealloc
    if (wid == 0) {
        asm volatile("tcgen05.dealloc.cta_group::2.sync.aligned.b32 %0, %1;"
                     :: "r"(tmem), "r"(512u));
    }
    CLUSTER_SYNC_();
#else
    (void)tmAh; (void)tmAl; (void)tmB; (void)scales; (void)zps; (void)biasv;
    (void)rowsum; (void)rscale; (void)out;
#endif
}

// ============================================================================
// Host launcher
// ============================================================================
typedef CUresult (*tme_fn_t)(CUtensorMap*, CUtensorMapDataType, cuuint32_t, void*,
                             const cuuint64_t*, const cuuint64_t*,
                             const cuuint32_t*, const cuuint32_t*,
                             CUtensorMapInterleave, CUtensorMapSwizzle,
                             CUtensorMapL2promotion, CUtensorMapFloatOOBfill);

extern "C" void kernel_launch(void* const* d_in, const int* in_sizes, int n_in,
                              void* d_out, int out_size) {
    const float* input  = (const float*)d_in[0];
    const int*   w      = (const int*)d_in[1];
    const float* scales = (const float*)d_in[2];
    const float* zps    = (const float*)d_in[3];
    const float* bias   = (const float*)d_in[4];
    float* out = (float*)d_out;
    (void)in_sizes; (void)n_in; (void)out_size;

    void *pW = nullptr, *pAh = nullptr, *pAl = nullptr, *pRs = nullptr, *pSc = nullptr;
    cudaGetSymbolAddress(&pW,  g_W8);
    cudaGetSymbolAddress(&pAh, g_Ah);
    cudaGetSymbolAddress(&pAl, g_Al);
    cudaGetSymbolAddress(&pRs, g_rowsum);
    cudaGetSymbolAddress(&pSc, g_rscale);

    tme_fn_t encode = nullptr;
    cudaDriverEntryPointQueryResult qr;
    cudaGetDriverEntryPoint("cuTensorMapEncodeTiled", (void**)&encode,
                            cudaEnableDefault, &qr);

    CUtensorMap mAh, mAl, mB;
    __builtin_memset(&mAh, 0, sizeof(mAh));
    __builtin_memset(&mAl, 0, sizeof(mAl));
    __builtin_memset(&mB, 0, sizeof(mB));
    if (encode) {
        {
            cuuint64_t dims[3]    = { IN_F, TOKENS, 1 };
            cuuint64_t strides[2] = { IN_F, (cuuint64_t)IN_F * TOKENS };
            cuuint32_t box[3]     = { KC, 128, 1 };    // 64B rows (SW64)
            cuuint32_t es[3]      = { 1, 1, 1 };
            encode(&mAh, CU_TENSOR_MAP_DATA_TYPE_UINT8, 3, pAh, dims, strides, box, es,
                   CU_TENSOR_MAP_INTERLEAVE_NONE, CU_TENSOR_MAP_SWIZZLE_64B,
                   CU_TENSOR_MAP_L2_PROMOTION_L2_128B, CU_TENSOR_MAP_FLOAT_OOB_FILL_NONE);
            encode(&mAl, CU_TENSOR_MAP_DATA_TYPE_UINT8, 3, pAl, dims, strides, box, es,
                   CU_TENSOR_MAP_INTERLEAVE_NONE, CU_TENSOR_MAP_SWIZZLE_64B,
                   CU_TENSOR_MAP_L2_PROMOTION_L2_128B, CU_TENSOR_MAP_FLOAT_OOB_FILL_NONE);
        }
        {
            cuuint64_t dims[3]    = { IN_F, OUT_F, 1 };
            cuuint64_t strides[2] = { IN_F, (cuuint64_t)IN_F * OUT_F };
            cuuint32_t box[3]     = { KC, 128, 1 };    // 128-row pieces per CTA
            cuuint32_t es[3]      = { 1, 1, 1 };
            encode(&mB, CU_TENSOR_MAP_DATA_TYPE_UINT8, 3, pW, dims, strides, box, es,
                   CU_TENSOR_MAP_INTERLEAVE_NONE, CU_TENSOR_MAP_SWIZZLE_64B,
                   CU_TENSOR_MAP_L2_PROMOTION_L2_128B, CU_TENSOR_MAP_FLOAT_OOB_FILL_NONE);
        }
    }

    cudaFuncSetAttribute(qlinear_tc, cudaFuncAttributeMaxDynamicSharedMemorySize,
                         SMEM_TOTAL);

    // fused preprocessing: W pack + x two-digit quantization (overlapped)
    k_prep<<<NBLK_W + TOKENS, 256>>>((const int4*)w, (char4*)pW,
                                     (const float4*)input, (char4*)pAh, (char4*)pAl,
                                     (float*)pRs, (float*)pSc);

    // persistent GEMM: 148 CTAs = 74 cg2 pairs
    qlinear_tc<<<dim3(2 * NPAIR, 1), 192, SMEM_TOTAL>>>(
        mAh, mAl, mB, scales, zps, bias,
        (const float*)pRs, (const float*)pSc, out);
}